// round 13
// baseline (speedup 1.0000x reference)
#include <cuda_runtime.h>
#include <cuda_bf16.h>
#include <cstdint>

#define BB 8
#define SS 1024
#define DD 1024
#define HH 8
#define DH 128
#define NN 3072
#define SCALE 0.08838834764831845f   // 1/sqrt(128)

// ---------------------------------------------------------------------------
// Device scratch
// ---------------------------------------------------------------------------
__device__ __nv_bfloat16 g_kh[BB*HH*SS*DH];   // K hi  [bh][s][d]
__device__ __nv_bfloat16 g_kl[BB*HH*SS*DH];   // K lo
__device__ __nv_bfloat16 g_qh[BB*HH*SS*DH];   // Q hi  [bh][s][d]
__device__ __nv_bfloat16 g_ql[BB*HH*SS*DH];   // Q lo
__device__ __nv_bfloat16 g_vth[BB*HH*DH*SS];  // V^T hi [bh][d][s]
__device__ __nv_bfloat16 g_Ah[BB*SS*DD];
__device__ __nv_bfloat16 g_Al[BB*SS*DD];
__device__ __nv_bfloat16 g_Wh[NN*DD];
__device__ __nv_bfloat16 g_Wl[NN*DD];

// ---------------------------------------------------------------------------
// Split conversion (merged A + W kernel)
// ---------------------------------------------------------------------------
__device__ __forceinline__ void split4(float4 v, __nv_bfloat162* hi2, __nv_bfloat162* lo2) {
    __nv_bfloat16 hx = __float2bfloat16_rn(v.x);
    __nv_bfloat16 hy = __float2bfloat16_rn(v.y);
    __nv_bfloat16 hz = __float2bfloat16_rn(v.z);
    __nv_bfloat16 hw = __float2bfloat16_rn(v.w);
    hi2[0] = __nv_bfloat162(hx, hy);
    hi2[1] = __nv_bfloat162(hz, hw);
    lo2[0] = __nv_bfloat162(__float2bfloat16_rn(v.x - __bfloat162float(hx)),
                            __float2bfloat16_rn(v.y - __bfloat162float(hy)));
    lo2[1] = __nv_bfloat162(__float2bfloat16_rn(v.z - __bfloat162float(hz)),
                            __float2bfloat16_rn(v.w - __bfloat162float(hw)));
}

#define A_I4 (BB*SS*DD/4)
#define W_I4 (NN*DD/4)

__global__ __launch_bounds__(256) void conv_kernel(const float* __restrict__ A,
                                                   const float* __restrict__ c_w,
                                                   const float* __restrict__ v_w) {
    int i4 = blockIdx.x * 256 + threadIdx.x;
    if (i4 < A_I4) {
        float4 v = ((const float4*)A)[i4];
        __nv_bfloat162 h[2], l[2];
        split4(v, h, l);
        ((__nv_bfloat162*)g_Ah)[i4*2]   = h[0];
        ((__nv_bfloat162*)g_Ah)[i4*2+1] = h[1];
        ((__nv_bfloat162*)g_Al)[i4*2]   = l[0];
        ((__nv_bfloat162*)g_Al)[i4*2+1] = l[1];
    } else {
        int w4 = i4 - A_I4;
        if (w4 >= W_I4) return;
        int e = w4 * 4;
        int n = e >> 10, k = e & 1023;
        const float* src = (n < DD) ? (v_w + (size_t)n * DD + k)
                                    : (c_w + (size_t)(n - DD) * DD + k);
        float4 v = *(const float4*)src;
        __nv_bfloat162 h[2], l[2];
        split4(v, h, l);
        ((__nv_bfloat162*)g_Wh)[w4*2]   = h[0];
        ((__nv_bfloat162*)g_Wh)[w4*2+1] = h[1];
        ((__nv_bfloat162*)g_Wl)[w4*2]   = l[0];
        ((__nv_bfloat162*)g_Wl)[w4*2+1] = l[1];
    }
}

// ---------------------------------------------------------------------------
// helpers
// ---------------------------------------------------------------------------
__device__ __forceinline__ uint32_t smem_u32(const void* p) {
    uint32_t a;
    asm("{ .reg .u64 t; cvta.to.shared.u64 t, %1; cvt.u32.u64 %0, t; }" : "=r"(a) : "l"(p));
    return a;
}
__device__ __forceinline__ void ldsm_x4(uint32_t* r, uint32_t addr) {
    asm volatile("ldmatrix.sync.aligned.m8n8.x4.shared.b16 {%0,%1,%2,%3}, [%4];"
                 : "=r"(r[0]), "=r"(r[1]), "=r"(r[2]), "=r"(r[3]) : "r"(addr));
}
__device__ __forceinline__ void mma_bf16(float* c, const uint32_t* a, uint32_t b0, uint32_t b1) {
    asm volatile(
        "mma.sync.aligned.m16n8k16.row.col.f32.bf16.bf16.f32 "
        "{%0,%1,%2,%3}, {%4,%5,%6,%7}, {%8,%9}, {%0,%1,%2,%3};"
        : "+f"(c[0]), "+f"(c[1]), "+f"(c[2]), "+f"(c[3])
        : "r"(a[0]), "r"(a[1]), "r"(a[2]), "r"(a[3]), "r"(b0), "r"(b1));
}
__device__ __forceinline__ void cpa16ca(uint32_t dst, const void* src) {
    asm volatile("cp.async.ca.shared.global [%0], [%1], 16;" :: "r"(dst), "l"(src));
}
__device__ __forceinline__ void cpa16cg(uint32_t dst, const void* src) {
    asm volatile("cp.async.cg.shared.global [%0], [%1], 16;" :: "r"(dst), "l"(src));
}
#define CP_COMMIT() asm volatile("cp.async.commit_group;")
#define CP_WAIT(n)  asm volatile("cp.async.wait_group %0;" :: "n"(n))

__device__ __forceinline__ void store_hilo(__nv_bfloat16* bh_, __nv_bfloat16* bl_,
                                           size_t off, float x0, float x1) {
    __nv_bfloat16 h0 = __float2bfloat16_rn(x0), h1 = __float2bfloat16_rn(x1);
    *(__nv_bfloat162*)(bh_ + off) = __nv_bfloat162(h0, h1);
    *(__nv_bfloat162*)(bl_ + off) =
        __nv_bfloat162(__float2bfloat16_rn(x0 - __bfloat162float(h0)),
                       __float2bfloat16_rn(x1 - __bfloat162float(h1)));
}

// ---------------------------------------------------------------------------
// Projection GEMM (split-bf16 HMMA): K/Q 3 passes, V 1 pass. occ 2.
// ---------------------------------------------------------------------------
#define KC 32
#define ROWP 40
#define BUF_E (128*ROWP)
#define OFF_AH 0
#define OFF_AL (2*BUF_E)
#define OFF_BH (4*BUF_E)
#define OFF_BL (6*BUF_E)
#define GEMM_SMEM_B (8*BUF_E*2 + 512)

__device__ __forceinline__ void issue_op(uint32_t sdst, const __nv_bfloat16* g,
                                         int tid, int k0) {
#pragma unroll
    for (int j = 0; j < 2; j++) {
        int u = tid + j * 256;
        int row = u >> 2, seg = u & 3;
        cpa16ca(sdst + (uint32_t)(row * ROWP + seg * 8) * 2,
                g + (size_t)row * DD + k0 + seg * 8);
    }
}

__global__ __launch_bounds__(256, 2) void gemm_kernel(const float* __restrict__ c_b,
                                                      const float* __restrict__ v_b) {
    extern __shared__ __nv_bfloat16 sm[];
    float* sBias = (float*)(sm + 8 * BUF_E);
    const uint32_t sbase = smem_u32(sm);

    const int tid  = threadIdx.x;
    const int lane = tid & 31;
    const int wid  = tid >> 5;
    const int wm   = wid >> 1;
    const int wn   = wid & 1;
    const int n0   = blockIdx.x * 128;
    const int m0   = blockIdx.y * 128;
    const int kind = n0 >> 10;
    const bool vpath = (kind == 2);

    const __nv_bfloat16* Ah = g_Ah + (size_t)m0 * DD;
    const __nv_bfloat16* Al = g_Al + (size_t)m0 * DD;
    const __nv_bfloat16* Bh = g_Wh + (size_t)n0 * DD;
    const __nv_bfloat16* Bl = g_Wl + (size_t)n0 * DD;

    const float* bp = (n0 < DD) ? (v_b + n0) : (c_b + (n0 - DD));
    if (tid < 128) sBias[tid] = bp[tid];

    float acc[2][8][4];
#pragma unroll
    for (int i = 0; i < 2; i++)
#pragma unroll
        for (int j = 0; j < 8; j++)
#pragma unroll
            for (int c = 0; c < 4; c++) acc[i][j][c] = 0.f;

    const int lrow_a = wm * 32 + (lane & 15);
    const int lrow_b0 = wn * 64 + (lane & 15);
    const int lk = ((lane >> 4) & 1) * 8;

    {
        issue_op(sbase + OFF_AH * 2, Ah, tid, 0);
        issue_op(sbase + OFF_BH * 2, Bh, tid, 0);
        if (!vpath) {
            issue_op(sbase + OFF_AL * 2, Al, tid, 0);
            issue_op(sbase + OFF_BL * 2, Bl, tid, 0);
        }
        CP_COMMIT();
    }

#pragma unroll 1
    for (int c = 0; c < DD / KC; c++) {
        const int cur = c & 1;
        if (c + 1 < DD / KC) {
            uint32_t bu = sbase + (uint32_t)((cur ^ 1) * BUF_E) * 2;
            int k0 = (c + 1) * KC;
            issue_op(bu + OFF_AH * 2, Ah, tid, k0);
            issue_op(bu + OFF_BH * 2, Bh, tid, k0);
            if (!vpath) {
                issue_op(bu + OFF_AL * 2, Al, tid, k0);
                issue_op(bu + OFF_BL * 2, Bl, tid, k0);
            }
            CP_COMMIT();
            CP_WAIT(1);
        } else {
            CP_WAIT(0);
        }
        __syncthreads();

        const __nv_bfloat16* base = sm + cur * BUF_E;
#pragma unroll
        for (int kk = 0; kk < 2; kk++) {
            const int ke = kk * 16 + lk;
            uint32_t ah[2][4], al[2][4], bh[4][4], bl[4][4];
#pragma unroll
            for (int mi = 0; mi < 2; mi++) {
                uint32_t ad = smem_u32(base + OFF_AH + (lrow_a + mi * 16) * ROWP + ke);
                ldsm_x4(ah[mi], ad);
                if (!vpath) ldsm_x4(al[mi], ad + (OFF_AL - OFF_AH) * 2);
            }
#pragma unroll
            for (int nb = 0; nb < 4; nb++) {
                uint32_t bd = smem_u32(base + OFF_BH + (lrow_b0 + nb * 16) * ROWP + ke);
                ldsm_x4(bh[nb], bd);
                if (!vpath) ldsm_x4(bl[nb], bd + (OFF_BL - OFF_BH) * 2);
            }
            if (vpath) {
#pragma unroll
                for (int mi = 0; mi < 2; mi++)
#pragma unroll
                    for (int nb = 0; nb < 4; nb++) {
                        mma_bf16(acc[mi][nb*2+0], ah[mi], bh[nb][0], bh[nb][2]);
                        mma_bf16(acc[mi][nb*2+1], ah[mi], bh[nb][1], bh[nb][3]);
                    }
            } else {
#pragma unroll
                for (int mi = 0; mi < 2; mi++)
#pragma unroll
                    for (int nb = 0; nb < 4; nb++) {
                        mma_bf16(acc[mi][nb*2+0], ah[mi], bh[nb][0], bh[nb][2]);
                        mma_bf16(acc[mi][nb*2+1], ah[mi], bh[nb][1], bh[nb][3]);
                        mma_bf16(acc[mi][nb*2+0], ah[mi], bl[nb][0], bl[nb][2]);
                        mma_bf16(acc[mi][nb*2+1], ah[mi], bl[nb][1], bl[nb][3]);
                        mma_bf16(acc[mi][nb*2+0], al[mi], bh[nb][0], bh[nb][2]);
                        mma_bf16(acc[mi][nb*2+1], al[mi], bh[nb][1], bh[nb][3]);
                    }
            }
        }
        __syncthreads();
    }

    const int h = (n0 >> 7) & 7;
    const int b_ = m0 >> 10;
    const int g = lane >> 2;
    const int tc = (lane & 3) * 2;
    const size_t bh_off = (size_t)(b_ * HH + h);

#pragma unroll
    for (int mi = 0; mi < 2; mi++) {
#pragma unroll
        for (int nj = 0; nj < 8; nj++) {
            const float* a4 = acc[mi][nj];
            int d = wn * 64 + nj * 8 + tc;
            float bx = sBias[d], by = sBias[d + 1];
            int s0 = (m0 + wm * 32 + mi * 16 + g) & 1023;
            float x0 = a4[0] + bx, x1 = a4[1] + by;
            float x2 = a4[2] + bx, x3 = a4[3] + by;
            if (kind == 2) {
                __nv_bfloat16* dst = g_vth + bh_off * DH * SS;
                dst[(size_t)d * SS + s0]           = __float2bfloat16_rn(x0);
                dst[(size_t)(d + 1) * SS + s0]     = __float2bfloat16_rn(x1);
                dst[(size_t)d * SS + s0 + 8]       = __float2bfloat16_rn(x2);
                dst[(size_t)(d + 1) * SS + s0 + 8] = __float2bfloat16_rn(x3);
            } else {
                __nv_bfloat16* dh_ = (kind == 0) ? g_kh : g_qh;
                __nv_bfloat16* dl_ = (kind == 0) ? g_kl : g_ql;
                size_t base_off = (bh_off * SS + s0) * DH + d;
                store_hilo(dh_, dl_, base_off, x0, x1);
                store_hilo(dh_, dl_, base_off + 8 * DH, x2, x3);
            }
        }
    }
}

// ---------------------------------------------------------------------------
// Monolithic attention v3, TI=64, occ 2, pipelined phase 3.
// ---------------------------------------------------------------------------
#define KP 136
#define EPITCH 132                     // floats
#define VPITCH 136
#define PPITCH 136
#define SOFF_K    0                    // P1: Kh(17408)+Kl(17408) | P3: P(17408)
#define SOFF_KL   17408
#define SOFF_U    34816                // P1: Qh+Ql | P3: E(33792)+V(34816)
#define SOFF_E    SOFF_U
#define SOFF_V    (SOFF_U + 33792)     // 68608
#define SOFF_MASK 104448
#define SOFF_SUM  108544               // 64 floats
#define SOFF_INV  108800               // 64 floats
#define ATTN_SMEM 109056

__global__ __launch_bounds__(256, 2) void attn_kernel(
    const float* __restrict__ m_feats,
    const int*   __restrict__ mask,
    float* __restrict__ out)
{
    extern __shared__ char smc[];
    int*   sMask = (int*)(smc + SOFF_MASK);
    float* sSum  = (float*)(smc + SOFF_SUM);
    float* sInv  = (float*)(smc + SOFF_INV);
    float*         sE  = (float*)(smc + SOFF_E);
    __nv_bfloat16* sPh = (__nv_bfloat16*)(smc + SOFF_K);
    const uint32_t uKh = smem_u32(smc) + SOFF_K;
    const uint32_t uQh = smem_u32(smc) + SOFF_U;
    const uint32_t uE  = smem_u32(smc) + SOFF_E;
    const uint32_t uV  = smem_u32(smc) + SOFF_V;
    const uint32_t uP  = smem_u32(smc) + SOFF_K;

    const int tid  = threadIdx.x;
    const int lane = tid & 31;
    const int wid  = tid >> 5;
    const int b  = blockIdx.z;
    const int h  = blockIdx.y;
    const int i0 = blockIdx.x * 64;
    const size_t bh = (size_t)(b * HH + h);
    const size_t wbase = (size_t)BB * SS * DD + (bh * SS + i0) * SS;

    const int wm = wid >> 2;        // 0..1
    const int wn = wid & 3;         // 0..3
    const int lr16 = lane & 15;
    const int lkb = (lane >> 4) * 8;
    const int grow = lane >> 2;
    const int gcol = (lane & 3) * 2;

    if (tid < 64) sSum[tid] = 0.f;
    // Prologue: K tile + Q chunk 0 issued together (one drain)
#pragma unroll
    for (int it = 0; it < 4; it++) {
        int p = tid + it * 256;
        int row = p >> 4, seg = p & 15;
        size_t go = (bh * SS + i0 + row) * DH + seg * 8;
        uint32_t so = (uint32_t)(row * KP + seg * 8) * 2;
        cpa16cg(uKh + so, g_kh + go);
        cpa16cg(uKh + (SOFF_KL - SOFF_K) + so, g_kl + go);
    }
#pragma unroll
    for (int it = 0; it < 8; it++) {
        int p = tid + it * 256;
        int row = p >> 4, seg = p & 15;
        size_t go = (bh * SS + row) * DH + seg * 8;
        uint32_t so = (uint32_t)(row * KP + seg * 8) * 2;
        cpa16cg(uQh + so, g_qh + go);
        cpa16cg(uQh + 34816 + so, g_ql + go);
    }
    CP_COMMIT();
    for (int j = tid; j < SS; j += 256) sMask[j] = mask[b * SS + j];

    // ================= Phase 1: e = exp(score) -> global; sums in regs ======
    float psum[2][2] = {{0.f, 0.f}, {0.f, 0.f}};
#pragma unroll 1
    for (int ct = 0; ct < 8; ct++) {
        CP_WAIT(0);
        __syncthreads();

        float acc[2][4][4];
#pragma unroll
        for (int i = 0; i < 2; i++)
#pragma unroll
            for (int j = 0; j < 4; j++)
#pragma unroll
                for (int cc = 0; cc < 4; cc++) acc[i][j][cc] = 0.f;

#pragma unroll
        for (int ks = 0; ks < 8; ks++) {
            const int ke = ks * 16 + lkb;
            uint32_t kh[2][4], kl[2][4], qh[2][4], ql[2][4];
#pragma unroll
            for (int mi = 0; mi < 2; mi++) {
                uint32_t ad = uKh + (uint32_t)((wm * 32 + mi * 16 + lr16) * KP + ke) * 2;
                ldsm_x4(kh[mi], ad);
                ldsm_x4(kl[mi], ad + (SOFF_KL - SOFF_K));
            }
#pragma unroll
            for (int nb = 0; nb < 2; nb++) {
                uint32_t bd = uQh + (uint32_t)((wn * 32 + nb * 16 + lr16) * KP + ke) * 2;
                ldsm_x4(qh[nb], bd);
                ldsm_x4(ql[nb], bd + 34816);
            }
#pragma unroll
            for (int mi = 0; mi < 2; mi++)
#pragma unroll
                for (int nb = 0; nb < 2; nb++) {
                    mma_bf16(acc[mi][nb*2+0], kh[mi], qh[nb][0], qh[nb][2]);
                    mma_bf16(acc[mi][nb*2+1], kh[mi], qh[nb][1], qh[nb][3]);
                    mma_bf16(acc[mi][nb*2+0], kh[mi], ql[nb][0], ql[nb][2]);
                    mma_bf16(acc[mi][nb*2+1], kh[mi], ql[nb][1], ql[nb][3]);
                    mma_bf16(acc[mi][nb*2+0], kl[mi], qh[nb][0], qh[nb][2]);
                    mma_bf16(acc[mi][nb*2+1], kl[mi], qh[nb][1], qh[nb][3]);
                }
        }

#pragma unroll
        for (int mi = 0; mi < 2; mi++)
#pragma unroll
            for (int nj = 0; nj < 4; nj++) {
                int jg = ct * 128 + wn * 32 + (nj >> 1) * 16 + (nj & 1) * 8 + gcol;
                bool m0 = sMask[jg] != 0, m1 = sMask[jg + 1] != 0;
                int ir = wm * 32 + mi * 16 + grow;
                const float* a4 = acc[mi][nj];
                float2 r0, r1;
                r0.x = m0 ? __expf(a4[0] * SCALE) : 1e-37f;
                r0.y = m1 ? __expf(a4[1] * SCALE) : 1e-37f;
                r1.x = m0 ? __expf(a4[2] * SCALE) : 1e-37f;
                r1.y = m1 ? __expf(a4[3] * SCALE) : 1e-37f;
                psum[mi][0] += r0.x + r0.y;
                psum[mi][1] += r1.x + r1.y;
                *(float2*)&out[wbase + (size_t)ir * SS + jg]       = r0;
                *(float2*)&out[wbase + (size_t)(ir + 8) * SS + jg] = r1;
            }
        __syncthreads();

        if (ct + 1 < 8) {
#pragma unroll
            for (int it = 0; it < 8; it++) {
                int p = tid + it * 256;
                int row = p >> 4, seg = p & 15;
                size_t go = (bh * SS + (ct + 1) * 128 + row) * DH + seg * 8;
                uint32_t so = (uint32_t)(row * KP + seg * 8) * 2;
                cpa16cg(uQh + so, g_qh + go);
                cpa16cg(uQh + 34816 + so, g_ql + go);
            }
            CP_COMMIT();
        }
    }

    // row-sum reduction -> sInv (SMEM only)
#pragma unroll
    for (int mi = 0; mi < 2; mi++)
#pragma unroll
        for (int hf = 0; hf < 2; hf++) {
            psum[mi][hf] += __shfl_xor_sync(~0u, psum[mi][hf], 1);
            psum[mi][hf] += __shfl_xor_sync(~0u, psum[mi][hf], 2);
        }
    if ((lane & 3) == 0) {
#pragma unroll
        for (int mi = 0; mi < 2; mi++) {
            atomicAdd(&sSum[wm * 32 + mi * 16 + grow],     psum[mi][0]);
            atomicAdd(&sSum[wm * 32 + mi * 16 + grow + 8], psum[mi][1]);
        }
    }
    __syncthreads();
    if (tid < 64) sInv[tid] = 1.0f / sSum[tid];
    __threadfence_block();
    __syncthreads();

    // ================= Phase 3: pipelined normalize + PV ====================
    float racc[2][4][4];
#pragma unroll
    for (int i = 0; i < 2; i++)
#pragma unroll
        for (int j = 0; j < 4; j++)
#pragma unroll
            for (int cc = 0; cc < 4; cc++) racc[i][j][cc] = 0.f;

    const int crow = tid >> 2;          // 0..63
    const int cq   = tid & 3;

    // prologue: issue E0 (group), V0 (group)
#pragma unroll
    for (int it = 0; it < 8; it++) {
        int p = tid + it * 256;
        int row = p >> 5, seg = p & 31;
        cpa16cg(uE + (uint32_t)(row * EPITCH + seg * 4) * 4,
                out + wbase + (size_t)row * SS + seg * 4);
    }
    CP_COMMIT();
#pragma unroll
    for (int it = 0; it < 8; it++) {
        int p = tid + it * 256;
        int row = p >> 4, seg = p & 15;
        cpa16cg(uV + (uint32_t)(row * VPITCH + seg * 8) * 2,
                g_vth + (bh * DH + row) * SS + seg * 8);
    }
    CP_COMMIT();

#pragma unroll 1
    for (int jc = 0; jc < 8; jc++) {
        CP_WAIT(1);                 // E_jc ready (V_jc may be in flight)
        __syncthreads();

        // normalize from SMEM: w -> global, bf16 w -> P tile
        {
            float inv = sInv[crow];
            const float* erow = sE + crow * EPITCH;
            float* wrow = out + wbase + (size_t)crow * SS + jc * 128;
#pragma unroll
            for (int k = 0; k < 8; k++) {
                int col = cq * 4 + k * 16;
                float4 e4 = *(const float4*)&erow[col];
                float4 w4;
                w4.x = e4.x * inv; w4.y = e4.y * inv;
                w4.z = e4.z * inv; w4.w = e4.w * inv;
                *(float4*)&wrow[col] = w4;
                union { uint2 u; __nv_bfloat162 b2[2]; } pk;
                pk.b2[0] = __nv_bfloat162(__float2bfloat16_rn(w4.x), __float2bfloat16_rn(w4.y));
                pk.b2[1] = __nv_bfloat162(__float2bfloat16_rn(w4.z), __float2bfloat16_rn(w4.w));
                *(uint2*)&sPh[crow * PPITCH + col] = pk.u;
            }
        }
        __syncthreads();            // E consumed by all; P complete

        // prefetch E_{jc+1} (overlaps V wait + MMA)
        if (jc + 1 < 8) {
#pragma unroll
            for (int it = 0; it < 8; it++) {
                int p = tid + it * 256;
                int row = p >> 5, seg = p & 31;
                cpa16cg(uE + (uint32_t)(row * EPITCH + seg * 4) * 4,
                        out + wbase + (size_t)row * SS + (jc + 1) * 128 + seg * 4);
            }
            CP_COMMIT();
        }

        CP_WAIT(1);                 // V_jc ready (E_{jc+1} may be in flight)
        __syncthreads();

#pragma unroll
        for (int ks = 0; ks < 8; ks++) {
            const int ke = ks * 16 + lkb;
            uint32_t pa[2][4], vh[2][4];
#pragma unroll
            for (int mi = 0; mi < 2; mi++)
                ldsm_x4(pa[mi], uP + (uint32_t)((wm * 32 + mi * 16 + lr16) * PPITCH + ke) * 2);
#pragma unroll
            for (int nb = 0; nb < 2; nb++)
                ldsm_x4(vh[nb], uV + (uint32_t)((wn * 32 + nb * 16 + lr16) * VPITCH + ke) * 2);
#pragma unroll
            for (int mi = 0; mi < 2; mi++)
#pragma unroll
                for (int nb = 0; nb < 2; nb++) {
                    mma_bf16(racc[mi][nb*2+0], pa[mi], vh[nb][0], vh[nb][2]);
                    mma_bf16(racc[mi][nb*2+1], pa[mi], vh[nb][1], vh[nb][3]);
                }
        }
        __syncthreads();            // V consumed

        // prefetch V_{jc+1}
        if (jc + 1 < 8) {
#pragma unroll
            for (int it = 0; it < 8; it++) {
                int p = tid + it * 256;
                int row = p >> 4, seg = p & 15;
                cpa16cg(uV + (uint32_t)(row * VPITCH + seg * 8) * 2,
                        g_vth + (bh * DH + row) * SS + (jc + 1) * 128 + seg * 8);
            }
            CP_COMMIT();
        }
    }

    // epilogue: out = m_feats + R (P normalized)
#pragma unroll
    for (int mi = 0; mi < 2; mi++)
#pragma unroll
        for (int nj = 0; nj < 4; nj++) {
            int d = wn * 32 + (nj >> 1) * 16 + (nj & 1) * 8 + gcol;
            int ir = wm * 32 + mi * 16 + grow;
            const float* a4 = racc[mi][nj];
            size_t o0 = ((size_t)b * SS + i0 + ir) * DD + h * DH + d;
            float2 mf0 = *(const float2*)&m_feats[o0];
            *(float2*)&out[o0] = make_float2(mf0.x + a4[0], mf0.y + a4[1]);
            size_t o1 = o0 + (size_t)8 * DD;
            float2 mf1 = *(const float2*)&m_feats[o1];
            *(float2*)&out[o1] = make_float2(mf1.x + a4[2], mf1.y + a4[3]);
        }
}

// ---------------------------------------------------------------------------
extern "C" void kernel_launch(void* const* d_in, const int* in_sizes, int n_in,
                              void* d_out, int out_size)
{
    const float* m_feats = (const float*)d_in[0];
    const int*   mask    = (const int*)d_in[1];
    const float* c_w     = (const float*)d_in[2];
    const float* c_b     = (const float*)d_in[3];
    const float* v_w     = (const float*)d_in[4];
    const float* v_b     = (const float*)d_in[5];
    float* out = (float*)d_out;

    conv_kernel<<<(A_I4 + W_I4 + 255) / 256, 256>>>(m_feats, c_w, v_w);

    cudaFuncSetAttribute(gemm_kernel,
                         cudaFuncAttributeMaxDynamicSharedMemorySize, GEMM_SMEM_B);
    dim3 gG(NN / 128, BB * SS / 128);
    gemm_kernel<<<gG, 256, GEMM_SMEM_B>>>(c_b, v_b);

    cudaFuncSetAttribute(attn_kernel,
                         cudaFuncAttributeMaxDynamicSharedMemorySize, ATTN_SMEM);
    dim3 gB(SS / 64, HH, BB);
    attn_kernel<<<gB, 256, ATTN_SMEM>>>(m_feats, mask, out);
}

// round 14
// speedup vs baseline: 1.0070x; 1.0070x over previous
#include <cuda_runtime.h>
#include <cuda_bf16.h>
#include <cstdint>

#define BB 8
#define SS 1024
#define DD 1024
#define HH 8
#define DH 128
#define NN 3072
#define SCALE 0.08838834764831845f   // 1/sqrt(128)

// ---------------------------------------------------------------------------
// Device scratch
// ---------------------------------------------------------------------------
__device__ __nv_bfloat16 g_kh[BB*HH*SS*DH];   // K hi  [bh][s][d]
__device__ __nv_bfloat16 g_kl[BB*HH*SS*DH];   // K lo
__device__ __nv_bfloat16 g_qh[BB*HH*SS*DH];   // Q hi  [bh][s][d]
__device__ __nv_bfloat16 g_ql[BB*HH*SS*DH];   // Q lo
__device__ __nv_bfloat16 g_vth[BB*HH*DH*SS];  // V^T hi [bh][d][s]
__device__ __nv_bfloat16 g_Ah[BB*SS*DD];
__device__ __nv_bfloat16 g_Al[BB*SS*DD];
__device__ __nv_bfloat16 g_Wh[NN*DD];
__device__ __nv_bfloat16 g_Wl[NN*DD];

// ---------------------------------------------------------------------------
// Split conversion (merged A + W kernel)
// ---------------------------------------------------------------------------
__device__ __forceinline__ void split4(float4 v, __nv_bfloat162* hi2, __nv_bfloat162* lo2) {
    __nv_bfloat16 hx = __float2bfloat16_rn(v.x);
    __nv_bfloat16 hy = __float2bfloat16_rn(v.y);
    __nv_bfloat16 hz = __float2bfloat16_rn(v.z);
    __nv_bfloat16 hw = __float2bfloat16_rn(v.w);
    hi2[0] = __nv_bfloat162(hx, hy);
    hi2[1] = __nv_bfloat162(hz, hw);
    lo2[0] = __nv_bfloat162(__float2bfloat16_rn(v.x - __bfloat162float(hx)),
                            __float2bfloat16_rn(v.y - __bfloat162float(hy)));
    lo2[1] = __nv_bfloat162(__float2bfloat16_rn(v.z - __bfloat162float(hz)),
                            __float2bfloat16_rn(v.w - __bfloat162float(hw)));
}

#define A_I4 (BB*SS*DD/4)
#define W_I4 (NN*DD/4)

__global__ __launch_bounds__(256) void conv_kernel(const float* __restrict__ A,
                                                   const float* __restrict__ c_w,
                                                   const float* __restrict__ v_w) {
    int i4 = blockIdx.x * 256 + threadIdx.x;
    if (i4 < A_I4) {
        float4 v = ((const float4*)A)[i4];
        __nv_bfloat162 h[2], l[2];
        split4(v, h, l);
        ((__nv_bfloat162*)g_Ah)[i4*2]   = h[0];
        ((__nv_bfloat162*)g_Ah)[i4*2+1] = h[1];
        ((__nv_bfloat162*)g_Al)[i4*2]   = l[0];
        ((__nv_bfloat162*)g_Al)[i4*2+1] = l[1];
    } else {
        int w4 = i4 - A_I4;
        if (w4 >= W_I4) return;
        int e = w4 * 4;
        int n = e >> 10, k = e & 1023;
        const float* src = (n < DD) ? (v_w + (size_t)n * DD + k)
                                    : (c_w + (size_t)(n - DD) * DD + k);
        float4 v = *(const float4*)src;
        __nv_bfloat162 h[2], l[2];
        split4(v, h, l);
        ((__nv_bfloat162*)g_Wh)[w4*2]   = h[0];
        ((__nv_bfloat162*)g_Wh)[w4*2+1] = h[1];
        ((__nv_bfloat162*)g_Wl)[w4*2]   = l[0];
        ((__nv_bfloat162*)g_Wl)[w4*2+1] = l[1];
    }
}

// ---------------------------------------------------------------------------
// helpers
// ---------------------------------------------------------------------------
__device__ __forceinline__ uint32_t smem_u32(const void* p) {
    uint32_t a;
    asm("{ .reg .u64 t; cvta.to.shared.u64 t, %1; cvt.u32.u64 %0, t; }" : "=r"(a) : "l"(p));
    return a;
}
__device__ __forceinline__ void ldsm_x4(uint32_t* r, uint32_t addr) {
    asm volatile("ldmatrix.sync.aligned.m8n8.x4.shared.b16 {%0,%1,%2,%3}, [%4];"
                 : "=r"(r[0]), "=r"(r[1]), "=r"(r[2]), "=r"(r[3]) : "r"(addr));
}
__device__ __forceinline__ void mma_bf16(float* c, const uint32_t* a, uint32_t b0, uint32_t b1) {
    asm volatile(
        "mma.sync.aligned.m16n8k16.row.col.f32.bf16.bf16.f32 "
        "{%0,%1,%2,%3}, {%4,%5,%6,%7}, {%8,%9}, {%0,%1,%2,%3};"
        : "+f"(c[0]), "+f"(c[1]), "+f"(c[2]), "+f"(c[3])
        : "r"(a[0]), "r"(a[1]), "r"(a[2]), "r"(a[3]), "r"(b0), "r"(b1));
}
__device__ __forceinline__ void cpa16ca(uint32_t dst, const void* src) {
    asm volatile("cp.async.ca.shared.global [%0], [%1], 16;" :: "r"(dst), "l"(src));
}
__device__ __forceinline__ void cpa16cg(uint32_t dst, const void* src) {
    asm volatile("cp.async.cg.shared.global [%0], [%1], 16;" :: "r"(dst), "l"(src));
}
#define CP_COMMIT() asm volatile("cp.async.commit_group;")
#define CP_WAIT(n)  asm volatile("cp.async.wait_group %0;" :: "n"(n))

__device__ __forceinline__ void store_hilo(__nv_bfloat16* bh_, __nv_bfloat16* bl_,
                                           size_t off, float x0, float x1) {
    __nv_bfloat16 h0 = __float2bfloat16_rn(x0), h1 = __float2bfloat16_rn(x1);
    *(__nv_bfloat162*)(bh_ + off) = __nv_bfloat162(h0, h1);
    *(__nv_bfloat162*)(bl_ + off) =
        __nv_bfloat162(__float2bfloat16_rn(x0 - __bfloat162float(h0)),
                       __float2bfloat16_rn(x1 - __bfloat162float(h1)));
}

// ---------------------------------------------------------------------------
// Projection GEMM (split-bf16 HMMA): K/Q 3 passes, V 1 pass. occ 2.
// MMA passes ordered pass-major to break accumulator RAW chains.
// ---------------------------------------------------------------------------
#define KC 32
#define ROWP 40
#define BUF_E (128*ROWP)
#define OFF_AH 0
#define OFF_AL (2*BUF_E)
#define OFF_BH (4*BUF_E)
#define OFF_BL (6*BUF_E)
#define GEMM_SMEM_B (8*BUF_E*2 + 512)

__device__ __forceinline__ void issue_op(uint32_t sdst, const __nv_bfloat16* g,
                                         int tid, int k0) {
#pragma unroll
    for (int j = 0; j < 2; j++) {
        int u = tid + j * 256;
        int row = u >> 2, seg = u & 3;
        cpa16ca(sdst + (uint32_t)(row * ROWP + seg * 8) * 2,
                g + (size_t)row * DD + k0 + seg * 8);
    }
}

__global__ __launch_bounds__(256, 2) void gemm_kernel(const float* __restrict__ c_b,
                                                      const float* __restrict__ v_b) {
    extern __shared__ __nv_bfloat16 sm[];
    float* sBias = (float*)(sm + 8 * BUF_E);
    const uint32_t sbase = smem_u32(sm);

    const int tid  = threadIdx.x;
    const int lane = tid & 31;
    const int wid  = tid >> 5;
    const int wm   = wid >> 1;
    const int wn   = wid & 1;
    const int n0   = blockIdx.x * 128;
    const int m0   = blockIdx.y * 128;
    const int kind = n0 >> 10;
    const bool vpath = (kind == 2);

    const __nv_bfloat16* Ah = g_Ah + (size_t)m0 * DD;
    const __nv_bfloat16* Al = g_Al + (size_t)m0 * DD;
    const __nv_bfloat16* Bh = g_Wh + (size_t)n0 * DD;
    const __nv_bfloat16* Bl = g_Wl + (size_t)n0 * DD;

    const float* bp = (n0 < DD) ? (v_b + n0) : (c_b + (n0 - DD));
    if (tid < 128) sBias[tid] = bp[tid];

    float acc[2][8][4];
#pragma unroll
    for (int i = 0; i < 2; i++)
#pragma unroll
        for (int j = 0; j < 8; j++)
#pragma unroll
            for (int c = 0; c < 4; c++) acc[i][j][c] = 0.f;

    const int lrow_a = wm * 32 + (lane & 15);
    const int lrow_b0 = wn * 64 + (lane & 15);
    const int lk = ((lane >> 4) & 1) * 8;

    {
        issue_op(sbase + OFF_AH * 2, Ah, tid, 0);
        issue_op(sbase + OFF_BH * 2, Bh, tid, 0);
        if (!vpath) {
            issue_op(sbase + OFF_AL * 2, Al, tid, 0);
            issue_op(sbase + OFF_BL * 2, Bl, tid, 0);
        }
        CP_COMMIT();
    }

#pragma unroll 1
    for (int c = 0; c < DD / KC; c++) {
        const int cur = c & 1;
        if (c + 1 < DD / KC) {
            uint32_t bu = sbase + (uint32_t)((cur ^ 1) * BUF_E) * 2;
            int k0 = (c + 1) * KC;
            issue_op(bu + OFF_AH * 2, Ah, tid, k0);
            issue_op(bu + OFF_BH * 2, Bh, tid, k0);
            if (!vpath) {
                issue_op(bu + OFF_AL * 2, Al, tid, k0);
                issue_op(bu + OFF_BL * 2, Bl, tid, k0);
            }
            CP_COMMIT();
            CP_WAIT(1);
        } else {
            CP_WAIT(0);
        }
        __syncthreads();

        const __nv_bfloat16* base = sm + cur * BUF_E;
#pragma unroll
        for (int kk = 0; kk < 2; kk++) {
            const int ke = kk * 16 + lk;
            uint32_t ah[2][4], al[2][4], bh[4][4], bl[4][4];
#pragma unroll
            for (int mi = 0; mi < 2; mi++) {
                uint32_t ad = smem_u32(base + OFF_AH + (lrow_a + mi * 16) * ROWP + ke);
                ldsm_x4(ah[mi], ad);
                if (!vpath) ldsm_x4(al[mi], ad + (OFF_AL - OFF_AH) * 2);
            }
#pragma unroll
            for (int nb = 0; nb < 4; nb++) {
                uint32_t bd = smem_u32(base + OFF_BH + (lrow_b0 + nb * 16) * ROWP + ke);
                ldsm_x4(bh[nb], bd);
                if (!vpath) ldsm_x4(bl[nb], bd + (OFF_BL - OFF_BH) * 2);
            }
            // pass-major order: 16 independent MMAs between same-acc writes
#pragma unroll
            for (int mi = 0; mi < 2; mi++)
#pragma unroll
                for (int nb = 0; nb < 4; nb++) {
                    mma_bf16(acc[mi][nb*2+0], ah[mi], bh[nb][0], bh[nb][2]);
                    mma_bf16(acc[mi][nb*2+1], ah[mi], bh[nb][1], bh[nb][3]);
                }
            if (!vpath) {
#pragma unroll
                for (int mi = 0; mi < 2; mi++)
#pragma unroll
                    for (int nb = 0; nb < 4; nb++) {
                        mma_bf16(acc[mi][nb*2+0], ah[mi], bl[nb][0], bl[nb][2]);
                        mma_bf16(acc[mi][nb*2+1], ah[mi], bl[nb][1], bl[nb][3]);
                    }
#pragma unroll
                for (int mi = 0; mi < 2; mi++)
#pragma unroll
                    for (int nb = 0; nb < 4; nb++) {
                        mma_bf16(acc[mi][nb*2+0], al[mi], bh[nb][0], bh[nb][2]);
                        mma_bf16(acc[mi][nb*2+1], al[mi], bh[nb][1], bh[nb][3]);
                    }
            }
        }
        __syncthreads();
    }

    const int h = (n0 >> 7) & 7;
    const int b_ = m0 >> 10;
    const int g = lane >> 2;
    const int tc = (lane & 3) * 2;
    const size_t bh_off = (size_t)(b_ * HH + h);

#pragma unroll
    for (int mi = 0; mi < 2; mi++) {
#pragma unroll
        for (int nj = 0; nj < 8; nj++) {
            const float* a4 = acc[mi][nj];
            int d = wn * 64 + nj * 8 + tc;
            float bx = sBias[d], by = sBias[d + 1];
            int s0 = (m0 + wm * 32 + mi * 16 + g) & 1023;
            float x0 = a4[0] + bx, x1 = a4[1] + by;
            float x2 = a4[2] + bx, x3 = a4[3] + by;
            if (kind == 2) {
                __nv_bfloat16* dst = g_vth + bh_off * DH * SS;
                dst[(size_t)d * SS + s0]           = __float2bfloat16_rn(x0);
                dst[(size_t)(d + 1) * SS + s0]     = __float2bfloat16_rn(x1);
                dst[(size_t)d * SS + s0 + 8]       = __float2bfloat16_rn(x2);
                dst[(size_t)(d + 1) * SS + s0 + 8] = __float2bfloat16_rn(x3);
            } else {
                __nv_bfloat16* dh_ = (kind == 0) ? g_kh : g_qh;
                __nv_bfloat16* dl_ = (kind == 0) ? g_kl : g_ql;
                size_t base_off = (bh_off * SS + s0) * DH + d;
                store_hilo(dh_, dl_, base_off, x0, x1);
                store_hilo(dh_, dl_, base_off + 8 * DH, x2, x3);
            }
        }
    }
}

// ---------------------------------------------------------------------------
// Monolithic attention v3, TI=64, occ 2, pipelined phase 3.
// Phase-1 MMA passes pass-major (8 independent MMAs between same-acc writes).
// ---------------------------------------------------------------------------
#define KP 136
#define EPITCH 132                     // floats
#define VPITCH 136
#define PPITCH 136
#define SOFF_K    0                    // P1: Kh(17408)+Kl(17408) | P3: P(17408)
#define SOFF_KL   17408
#define SOFF_U    34816                // P1: Qh+Ql | P3: E(33792)+V(34816)
#define SOFF_E    SOFF_U
#define SOFF_V    (SOFF_U + 33792)     // 68608
#define SOFF_MASK 104448
#define SOFF_SUM  108544               // 64 floats
#define SOFF_INV  108800               // 64 floats
#define ATTN_SMEM 109056

__global__ __launch_bounds__(256, 2) void attn_kernel(
    const float* __restrict__ m_feats,
    const int*   __restrict__ mask,
    float* __restrict__ out)
{
    extern __shared__ char smc[];
    int*   sMask = (int*)(smc + SOFF_MASK);
    float* sSum  = (float*)(smc + SOFF_SUM);
    float* sInv  = (float*)(smc + SOFF_INV);
    float*         sE  = (float*)(smc + SOFF_E);
    __nv_bfloat16* sPh = (__nv_bfloat16*)(smc + SOFF_K);
    const uint32_t uKh = smem_u32(smc) + SOFF_K;
    const uint32_t uQh = smem_u32(smc) + SOFF_U;
    const uint32_t uE  = smem_u32(smc) + SOFF_E;
    const uint32_t uV  = smem_u32(smc) + SOFF_V;
    const uint32_t uP  = smem_u32(smc) + SOFF_K;

    const int tid  = threadIdx.x;
    const int lane = tid & 31;
    const int wid  = tid >> 5;
    const int b  = blockIdx.z;
    const int h  = blockIdx.y;
    const int i0 = blockIdx.x * 64;
    const size_t bh = (size_t)(b * HH + h);
    const size_t wbase = (size_t)BB * SS * DD + (bh * SS + i0) * SS;

    const int wm = wid >> 2;        // 0..1
    const int wn = wid & 3;         // 0..3
    const int lr16 = lane & 15;
    const int lkb = (lane >> 4) * 8;
    const int grow = lane >> 2;
    const int gcol = (lane & 3) * 2;

    if (tid < 64) sSum[tid] = 0.f;
    // Prologue: K tile + Q chunk 0 issued together (one drain)
#pragma unroll
    for (int it = 0; it < 4; it++) {
        int p = tid + it * 256;
        int row = p >> 4, seg = p & 15;
        size_t go = (bh * SS + i0 + row) * DH + seg * 8;
        uint32_t so = (uint32_t)(row * KP + seg * 8) * 2;
        cpa16cg(uKh + so, g_kh + go);
        cpa16cg(uKh + (SOFF_KL - SOFF_K) + so, g_kl + go);
    }
#pragma unroll
    for (int it = 0; it < 8; it++) {
        int p = tid + it * 256;
        int row = p >> 4, seg = p & 15;
        size_t go = (bh * SS + row) * DH + seg * 8;
        uint32_t so = (uint32_t)(row * KP + seg * 8) * 2;
        cpa16cg(uQh + so, g_qh + go);
        cpa16cg(uQh + 34816 + so, g_ql + go);
    }
    CP_COMMIT();
    for (int j = tid; j < SS; j += 256) sMask[j] = mask[b * SS + j];

    // ================= Phase 1: e = exp(score) -> global; sums in regs ======
    float psum[2][2] = {{0.f, 0.f}, {0.f, 0.f}};
#pragma unroll 1
    for (int ct = 0; ct < 8; ct++) {
        CP_WAIT(0);
        __syncthreads();

        float acc[2][4][4];
#pragma unroll
        for (int i = 0; i < 2; i++)
#pragma unroll
            for (int j = 0; j < 4; j++)
#pragma unroll
                for (int cc = 0; cc < 4; cc++) acc[i][j][cc] = 0.f;

#pragma unroll
        for (int ks = 0; ks < 8; ks++) {
            const int ke = ks * 16 + lkb;
            uint32_t kh[2][4], kl[2][4], qh[2][4], ql[2][4];
#pragma unroll
            for (int mi = 0; mi < 2; mi++) {
                uint32_t ad = uKh + (uint32_t)((wm * 32 + mi * 16 + lr16) * KP + ke) * 2;
                ldsm_x4(kh[mi], ad);
                ldsm_x4(kl[mi], ad + (SOFF_KL - SOFF_K));
            }
#pragma unroll
            for (int nb = 0; nb < 2; nb++) {
                uint32_t bd = uQh + (uint32_t)((wn * 32 + nb * 16 + lr16) * KP + ke) * 2;
                ldsm_x4(qh[nb], bd);
                ldsm_x4(ql[nb], bd + 34816);
            }
            // pass-major: 8 independent MMAs per pass
#pragma unroll
            for (int mi = 0; mi < 2; mi++)
#pragma unroll
                for (int nb = 0; nb < 2; nb++) {
                    mma_bf16(acc[mi][nb*2+0], kh[mi], qh[nb][0], qh[nb][2]);
                    mma_bf16(acc[mi][nb*2+1], kh[mi], qh[nb][1], qh[nb][3]);
                }
#pragma unroll
            for (int mi = 0; mi < 2; mi++)
#pragma unroll
                for (int nb = 0; nb < 2; nb++) {
                    mma_bf16(acc[mi][nb*2+0], kh[mi], ql[nb][0], ql[nb][2]);
                    mma_bf16(acc[mi][nb*2+1], kh[mi], ql[nb][1], ql[nb][3]);
                }
#pragma unroll
            for (int mi = 0; mi < 2; mi++)
#pragma unroll
                for (int nb = 0; nb < 2; nb++) {
                    mma_bf16(acc[mi][nb*2+0], kl[mi], qh[nb][0], qh[nb][2]);
                    mma_bf16(acc[mi][nb*2+1], kl[mi], qh[nb][1], qh[nb][3]);
                }
        }

#pragma unroll
        for (int mi = 0; mi < 2; mi++)
#pragma unroll
            for (int nj = 0; nj < 4; nj++) {
                int jg = ct * 128 + wn * 32 + (nj >> 1) * 16 + (nj & 1) * 8 + gcol;
                bool m0 = sMask[jg] != 0, m1 = sMask[jg + 1] != 0;
                int ir = wm * 32 + mi * 16 + grow;
                const float* a4 = acc[mi][nj];
                float2 r0, r1;
                r0.x = m0 ? __expf(a4[0] * SCALE) : 1e-37f;
                r0.y = m1 ? __expf(a4[1] * SCALE) : 1e-37f;
                r1.x = m0 ? __expf(a4[2] * SCALE) : 1e-37f;
                r1.y = m1 ? __expf(a4[3] * SCALE) : 1e-37f;
                psum[mi][0] += r0.x + r0.y;
                psum[mi][1] += r1.x + r1.y;
                *(float2*)&out[wbase + (size_t)ir * SS + jg]       = r0;
                *(float2*)&out[wbase + (size_t)(ir + 8) * SS + jg] = r1;
            }
        __syncthreads();

        if (ct + 1 < 8) {
#pragma unroll
            for (int it = 0; it < 8; it++) {
                int p = tid + it * 256;
                int row = p >> 4, seg = p & 15;
                size_t go = (bh * SS + (ct + 1) * 128 + row) * DH + seg * 8;
                uint32_t so = (uint32_t)(row * KP + seg * 8) * 2;
                cpa16cg(uQh + so, g_qh + go);
                cpa16cg(uQh + 34816 + so, g_ql + go);
            }
            CP_COMMIT();
        }
    }

    // row-sum reduction -> sInv (SMEM only)
#pragma unroll
    for (int mi = 0; mi < 2; mi++)
#pragma unroll
        for (int hf = 0; hf < 2; hf++) {
            psum[mi][hf] += __shfl_xor_sync(~0u, psum[mi][hf], 1);
            psum[mi][hf] += __shfl_xor_sync(~0u, psum[mi][hf], 2);
        }
    if ((lane & 3) == 0) {
#pragma unroll
        for (int mi = 0; mi < 2; mi++) {
            atomicAdd(&sSum[wm * 32 + mi * 16 + grow],     psum[mi][0]);
            atomicAdd(&sSum[wm * 32 + mi * 16 + grow + 8], psum[mi][1]);
        }
    }
    __syncthreads();
    if (tid < 64) sInv[tid] = 1.0f / sSum[tid];
    __threadfence_block();
    __syncthreads();

    // ================= Phase 3: pipelined normalize + PV ====================
    float racc[2][4][4];
#pragma unroll
    for (int i = 0; i < 2; i++)
#pragma unroll
        for (int j = 0; j < 4; j++)
#pragma unroll
            for (int cc = 0; cc < 4; cc++) racc[i][j][cc] = 0.f;

    const int crow = tid >> 2;          // 0..63
    const int cq   = tid & 3;

    // prologue: issue E0 (group), V0 (group)
#pragma unroll
    for (int it = 0; it < 8; it++) {
        int p = tid + it * 256;
        int row = p >> 5, seg = p & 31;
        cpa16cg(uE + (uint32_t)(row * EPITCH + seg * 4) * 4,
                out + wbase + (size_t)row * SS + seg * 4);
    }
    CP_COMMIT();
#pragma unroll
    for (int it = 0; it < 8; it++) {
        int p = tid + it * 256;
        int row = p >> 4, seg = p & 15;
        cpa16cg(uV + (uint32_t)(row * VPITCH + seg * 8) * 2,
                g_vth + (bh * DH + row) * SS + seg * 8);
    }
    CP_COMMIT();

#pragma unroll 1
    for (int jc = 0; jc < 8; jc++) {
        CP_WAIT(1);                 // E_jc ready (V_jc may be in flight)
        __syncthreads();

        // normalize from SMEM: w -> global, bf16 w -> P tile
        {
            float inv = sInv[crow];
            const float* erow = sE + crow * EPITCH;
            float* wrow = out + wbase + (size_t)crow * SS + jc * 128;
#pragma unroll
            for (int k = 0; k < 8; k++) {
                int col = cq * 4 + k * 16;
                float4 e4 = *(const float4*)&erow[col];
                float4 w4;
                w4.x = e4.x * inv; w4.y = e4.y * inv;
                w4.z = e4.z * inv; w4.w = e4.w * inv;
                *(float4*)&wrow[col] = w4;
                union { uint2 u; __nv_bfloat162 b2[2]; } pk;
                pk.b2[0] = __nv_bfloat162(__float2bfloat16_rn(w4.x), __float2bfloat16_rn(w4.y));
                pk.b2[1] = __nv_bfloat162(__float2bfloat16_rn(w4.z), __float2bfloat16_rn(w4.w));
                *(uint2*)&sPh[crow * PPITCH + col] = pk.u;
            }
        }
        __syncthreads();            // E consumed by all; P complete

        // prefetch E_{jc+1} (overlaps V wait + MMA)
        if (jc + 1 < 8) {
#pragma unroll
            for (int it = 0; it < 8; it++) {
                int p = tid + it * 256;
                int row = p >> 5, seg = p & 31;
                cpa16cg(uE + (uint32_t)(row * EPITCH + seg * 4) * 4,
                        out + wbase + (size_t)row * SS + (jc + 1) * 128 + seg * 4);
            }
            CP_COMMIT();
        }

        CP_WAIT(1);                 // V_jc ready (E_{jc+1} may be in flight)
        __syncthreads();

#pragma unroll
        for (int ks = 0; ks < 8; ks++) {
            const int ke = ks * 16 + lkb;
            uint32_t pa[2][4], vh[2][4];
#pragma unroll
            for (int mi = 0; mi < 2; mi++)
                ldsm_x4(pa[mi], uP + (uint32_t)((wm * 32 + mi * 16 + lr16) * PPITCH + ke) * 2);
#pragma unroll
            for (int nb = 0; nb < 2; nb++)
                ldsm_x4(vh[nb], uV + (uint32_t)((wn * 32 + nb * 16 + lr16) * VPITCH + ke) * 2);
#pragma unroll
            for (int mi = 0; mi < 2; mi++)
#pragma unroll
                for (int nb = 0; nb < 2; nb++) {
                    mma_bf16(racc[mi][nb*2+0], pa[mi], vh[nb][0], vh[nb][2]);
                    mma_bf16(racc[mi][nb*2+1], pa[mi], vh[nb][1], vh[nb][3]);
                }
        }
        __syncthreads();            // V consumed

        // prefetch V_{jc+1}
        if (jc + 1 < 8) {
#pragma unroll
            for (int it = 0; it < 8; it++) {
                int p = tid + it * 256;
                int row = p >> 4, seg = p & 15;
                cpa16cg(uV + (uint32_t)(row * VPITCH + seg * 8) * 2,
                        g_vth + (bh * DH + row) * SS + (jc + 1) * 128 + seg * 8);
            }
            CP_COMMIT();
        }
    }

    // epilogue: out = m_feats + R (P normalized)
#pragma unroll
    for (int mi = 0; mi < 2; mi++)
#pragma unroll
        for (int nj = 0; nj < 4; nj++) {
            int d = wn * 32 + (nj >> 1) * 16 + (nj & 1) * 8 + gcol;
            int ir = wm * 32 + mi * 16 + grow;
            const float* a4 = racc[mi][nj];
            size_t o0 = ((size_t)b * SS + i0 + ir) * DD + h * DH + d;
            float2 mf0 = *(const float2*)&m_feats[o0];
            *(float2*)&out[o0] = make_float2(mf0.x + a4[0], mf0.y + a4[1]);
            size_t o1 = o0 + (size_t)8 * DD;
            float2 mf1 = *(const float2*)&m_feats[o1];
            *(float2*)&out[o1] = make_float2(mf1.x + a4[2], mf1.y + a4[3]);
        }
}

// ---------------------------------------------------------------------------
extern "C" void kernel_launch(void* const* d_in, const int* in_sizes, int n_in,
                              void* d_out, int out_size)
{
    const float* m_feats = (const float*)d_in[0];
    const int*   mask    = (const int*)d_in[1];
    const float* c_w     = (const float*)d_in[2];
    const float* c_b     = (const float*)d_in[3];
    const float* v_w     = (const float*)d_in[4];
    const float* v_b     = (const float*)d_in[5];
    float* out = (float*)d_out;

    conv_kernel<<<(A_I4 + W_I4 + 255) / 256, 256>>>(m_feats, c_w, v_w);

    cudaFuncSetAttribute(gemm_kernel,
                         cudaFuncAttributeMaxDynamicSharedMemorySize, GEMM_SMEM_B);
    dim3 gG(NN / 128, BB * SS / 128);
    gemm_kernel<<<gG, 256, GEMM_SMEM_B>>>(c_b, v_b);

    cudaFuncSetAttribute(attn_kernel,
                         cudaFuncAttributeMaxDynamicSharedMemorySize, ATTN_SMEM);
    dim3 gB(SS / 64, HH, BB);
    attn_kernel<<<gB, 256, ATTN_SMEM>>>(m_feats, mask, out);
}

// round 15
// speedup vs baseline: 1.3564x; 1.3469x over previous
#include <cuda_runtime.h>
#include <cuda_fp16.h>
#include <cstdint>

#define BB 8
#define SS 1024
#define DD 1024
#define HH 8
#define DH 128
#define NN 3072
#define SCALE 0.08838834764831845f   // 1/sqrt(128)

// ---------------------------------------------------------------------------
// Device scratch (fp16 split: left operands hi+lo, right operands hi only)
// ---------------------------------------------------------------------------
__device__ __half g_kh[BB*HH*SS*DH];   // K hi  [bh][s][d]
__device__ __half g_kl[BB*HH*SS*DH];   // K lo
__device__ __half g_qh[BB*HH*SS*DH];   // Q hi  [bh][s][d]
__device__ __half g_vth[BB*HH*DH*SS];  // V^T hi [bh][d][s]
__device__ __half g_Ah[BB*SS*DD];      // m_feats hi
__device__ __half g_Al[BB*SS*DD];      // m_feats lo
__device__ __half g_Wh[NN*DD];         // [v_w ; c_w] hi

// ---------------------------------------------------------------------------
// Conversion kernel: A -> fp16 hi/lo; W -> fp16 hi
// ---------------------------------------------------------------------------
#define A_I4 (BB*SS*DD/4)
#define W_I4 (NN*DD/4)

__global__ __launch_bounds__(256) void conv_kernel(const float* __restrict__ A,
                                                   const float* __restrict__ c_w,
                                                   const float* __restrict__ v_w) {
    int i4 = blockIdx.x * 256 + threadIdx.x;
    if (i4 < A_I4) {
        float4 v = ((const float4*)A)[i4];
        __half hx = __float2half_rn(v.x), hy = __float2half_rn(v.y);
        __half hz = __float2half_rn(v.z), hw = __float2half_rn(v.w);
        ((__half2*)g_Ah)[i4*2]   = __halves2half2(hx, hy);
        ((__half2*)g_Ah)[i4*2+1] = __halves2half2(hz, hw);
        ((__half2*)g_Al)[i4*2]   = __floats2half2_rn(v.x - __half2float(hx),
                                                     v.y - __half2float(hy));
        ((__half2*)g_Al)[i4*2+1] = __floats2half2_rn(v.z - __half2float(hz),
                                                     v.w - __half2float(hw));
    } else {
        int w4 = i4 - A_I4;
        if (w4 >= W_I4) return;
        int e = w4 * 4;
        int n = e >> 10, k = e & 1023;
        const float* src = (n < DD) ? (v_w + (size_t)n * DD + k)
                                    : (c_w + (size_t)(n - DD) * DD + k);
        float4 v = *(const float4*)src;
        ((__half2*)g_Wh)[w4*2]   = __floats2half2_rn(v.x, v.y);
        ((__half2*)g_Wh)[w4*2+1] = __floats2half2_rn(v.z, v.w);
    }
}

// ---------------------------------------------------------------------------
// helpers
// ---------------------------------------------------------------------------
__device__ __forceinline__ uint32_t smem_u32(const void* p) {
    uint32_t a;
    asm("{ .reg .u64 t; cvta.to.shared.u64 t, %1; cvt.u32.u64 %0, t; }" : "=r"(a) : "l"(p));
    return a;
}
__device__ __forceinline__ void ldsm_x4(uint32_t* r, uint32_t addr) {
    asm volatile("ldmatrix.sync.aligned.m8n8.x4.shared.b16 {%0,%1,%2,%3}, [%4];"
                 : "=r"(r[0]), "=r"(r[1]), "=r"(r[2]), "=r"(r[3]) : "r"(addr));
}
__device__ __forceinline__ void mma_fp16(float* c, const uint32_t* a, uint32_t b0, uint32_t b1) {
    asm volatile(
        "mma.sync.aligned.m16n8k16.row.col.f32.f16.f16.f32 "
        "{%0,%1,%2,%3}, {%4,%5,%6,%7}, {%8,%9}, {%0,%1,%2,%3};"
        : "+f"(c[0]), "+f"(c[1]), "+f"(c[2]), "+f"(c[3])
        : "r"(a[0]), "r"(a[1]), "r"(a[2]), "r"(a[3]), "r"(b0), "r"(b1));
}
__device__ __forceinline__ void cpa16ca(uint32_t dst, const void* src) {
    asm volatile("cp.async.ca.shared.global [%0], [%1], 16;" :: "r"(dst), "l"(src));
}
__device__ __forceinline__ void cpa16cg(uint32_t dst, const void* src) {
    asm volatile("cp.async.cg.shared.global [%0], [%1], 16;" :: "r"(dst), "l"(src));
}
#define CP_COMMIT() asm volatile("cp.async.commit_group;")
#define CP_WAIT(n)  asm volatile("cp.async.wait_group %0;" :: "n"(n))

__device__ __forceinline__ void store_hilo_h(__half* hh_, __half* hl_,
                                             size_t off, float x0, float x1) {
    __half h0 = __float2half_rn(x0), h1 = __float2half_rn(x1);
    *(__half2*)(hh_ + off) = __halves2half2(h0, h1);
    *(__half2*)(hl_ + off) = __floats2half2_rn(x0 - __half2float(h0),
                                               x1 - __half2float(h1));
}

// ---------------------------------------------------------------------------
// Projection GEMM (fp16 split-left): K/Q 2 passes (Ah+Al)·Wh, V 1 pass. occ 2.
// ---------------------------------------------------------------------------
#define KC 32
#define ROWP 40
#define BUF_E (128*ROWP)
#define OFF_AH 0
#define OFF_AL BUF_E
#define OFF_BH (2*BUF_E)
#define GEMM_SMEM_B (6*BUF_E*2 + 512)   // 61952 bytes

__device__ __forceinline__ void issue_op(uint32_t sdst, const __half* g,
                                         int tid, int k0) {
#pragma unroll
    for (int j = 0; j < 2; j++) {
        int u = tid + j * 256;
        int row = u >> 2, seg = u & 3;
        cpa16ca(sdst + (uint32_t)(row * ROWP + seg * 8) * 2,
                g + (size_t)row * DD + k0 + seg * 8);
    }
}

__global__ __launch_bounds__(256, 2) void gemm_kernel(const float* __restrict__ c_b,
                                                      const float* __restrict__ v_b) {
    extern __shared__ __half sm[];
    float* sBias = (float*)(sm + 6 * BUF_E);
    const uint32_t sbase = smem_u32(sm);

    const int tid  = threadIdx.x;
    const int lane = tid & 31;
    const int wid  = tid >> 5;
    const int wm   = wid >> 1;
    const int wn   = wid & 1;
    const int n0   = blockIdx.x * 128;
    const int m0   = blockIdx.y * 128;
    const int kind = n0 >> 10;
    const bool vpath = (kind == 2);

    const __half* Ah = g_Ah + (size_t)m0 * DD;
    const __half* Al = g_Al + (size_t)m0 * DD;
    const __half* Bh = g_Wh + (size_t)n0 * DD;

    const float* bp = (n0 < DD) ? (v_b + n0) : (c_b + (n0 - DD));
    if (tid < 128) sBias[tid] = bp[tid];

    float acc[2][8][4];
#pragma unroll
    for (int i = 0; i < 2; i++)
#pragma unroll
        for (int j = 0; j < 8; j++)
#pragma unroll
            for (int c = 0; c < 4; c++) acc[i][j][c] = 0.f;

    const int lrow_a = wm * 32 + (lane & 15);
    const int lrow_b0 = wn * 64 + (lane & 15);
    const int lk = ((lane >> 4) & 1) * 8;

    {
        issue_op(sbase + OFF_AH * 2, Ah, tid, 0);
        issue_op(sbase + OFF_BH * 2, Bh, tid, 0);
        if (!vpath) issue_op(sbase + OFF_AL * 2, Al, tid, 0);
        CP_COMMIT();
    }

#pragma unroll 1
    for (int c = 0; c < DD / KC; c++) {
        const int cur = c & 1;
        if (c + 1 < DD / KC) {
            uint32_t bu = sbase + (uint32_t)((cur ^ 1) * 3 * BUF_E) * 2;
            int k0 = (c + 1) * KC;
            issue_op(bu + OFF_AH * 2, Ah, tid, k0);
            issue_op(bu + OFF_BH * 2, Bh, tid, k0);
            if (!vpath) issue_op(bu + OFF_AL * 2, Al, tid, k0);
            CP_COMMIT();
            CP_WAIT(1);
        } else {
            CP_WAIT(0);
        }
        __syncthreads();

        const __half* base = sm + cur * 3 * BUF_E;
#pragma unroll
        for (int kk = 0; kk < 2; kk++) {
            const int ke = kk * 16 + lk;
            uint32_t ah[2][4], al[2][4], bh[4][4];
#pragma unroll
            for (int mi = 0; mi < 2; mi++) {
                uint32_t ad = smem_u32(base + OFF_AH + (lrow_a + mi * 16) * ROWP + ke);
                ldsm_x4(ah[mi], ad);
                if (!vpath) ldsm_x4(al[mi], ad + (OFF_AL - OFF_AH) * 2);
            }
#pragma unroll
            for (int nb = 0; nb < 4; nb++) {
                uint32_t bd = smem_u32(base + OFF_BH + (lrow_b0 + nb * 16) * ROWP + ke);
                ldsm_x4(bh[nb], bd);
            }
            // pass 1: Ah·Bh
#pragma unroll
            for (int mi = 0; mi < 2; mi++)
#pragma unroll
                for (int nb = 0; nb < 4; nb++) {
                    mma_fp16(acc[mi][nb*2+0], ah[mi], bh[nb][0], bh[nb][2]);
                    mma_fp16(acc[mi][nb*2+1], ah[mi], bh[nb][1], bh[nb][3]);
                }
            // pass 2: Al·Bh (K/Q only)
            if (!vpath) {
#pragma unroll
                for (int mi = 0; mi < 2; mi++)
#pragma unroll
                    for (int nb = 0; nb < 4; nb++) {
                        mma_fp16(acc[mi][nb*2+0], al[mi], bh[nb][0], bh[nb][2]);
                        mma_fp16(acc[mi][nb*2+1], al[mi], bh[nb][1], bh[nb][3]);
                    }
            }
        }
        __syncthreads();
    }

    const int h = (n0 >> 7) & 7;
    const int b_ = m0 >> 10;
    const int g = lane >> 2;
    const int tc = (lane & 3) * 2;
    const size_t bh_off = (size_t)(b_ * HH + h);

#pragma unroll
    for (int mi = 0; mi < 2; mi++) {
#pragma unroll
        for (int nj = 0; nj < 8; nj++) {
            const float* a4 = acc[mi][nj];
            int d = wn * 64 + nj * 8 + tc;
            float bx = sBias[d], by = sBias[d + 1];
            int s0 = (m0 + wm * 32 + mi * 16 + g) & 1023;
            float x0 = a4[0] + bx, x1 = a4[1] + by;
            float x2 = a4[2] + bx, x3 = a4[3] + by;
            if (kind == 2) {
                __half* dst = g_vth + bh_off * DH * SS;
                dst[(size_t)d * SS + s0]           = __float2half_rn(x0);
                dst[(size_t)(d + 1) * SS + s0]     = __float2half_rn(x1);
                dst[(size_t)d * SS + s0 + 8]       = __float2half_rn(x2);
                dst[(size_t)(d + 1) * SS + s0 + 8] = __float2half_rn(x3);
            } else if (kind == 0) {
                size_t base_off = (bh_off * SS + s0) * DH + d;
                store_hilo_h(g_kh, g_kl, base_off, x0, x1);
                store_hilo_h(g_kh, g_kl, base_off + 8 * DH, x2, x3);
            } else {
                size_t base_off = (bh_off * SS + s0) * DH + d;
                *(__half2*)(g_qh + base_off)          = __floats2half2_rn(x0, x1);
                *(__half2*)(g_qh + base_off + 8 * DH) = __floats2half2_rn(x2, x3);
            }
        }
    }
}

// ---------------------------------------------------------------------------
// Monolithic attention, TI=64, occ 2. fp16 2-pass scores ((Kh+Kl)·Qh).
//   P1: e = exp(score*SCALE) -> out (w region); row sums -> sInv (SMEM)
//   P3: per 128-j chunk: cp.async e-tile + V; normalize from SMEM while V in
//       flight; w -> global once; fp16 P -> dead K region; fp16 PV MMA.
// ---------------------------------------------------------------------------
#define KP 136
#define EPITCH 132                     // floats
#define VPITCH 136
#define PPITCH 136
#define SOFF_K    0                    // P1: Kh(17408)+Kl(17408) | P3: P(17408)
#define SOFF_KL   17408
#define SOFF_U    34816                // P1: Qh(17408) | P3: E(33792)+V(34816)
#define SOFF_E    SOFF_U
#define SOFF_V    (SOFF_U + 33792)     // 68608
#define SOFF_MASK 103424
#define SOFF_SUM  107520               // 64 floats
#define SOFF_INV  107776               // 64 floats
#define ATTN_SMEM 108032

__global__ __launch_bounds__(256, 2) void attn_kernel(
    const float* __restrict__ m_feats,
    const int*   __restrict__ mask,
    float* __restrict__ out)
{
    extern __shared__ char smc[];
    int*   sMask = (int*)(smc + SOFF_MASK);
    float* sSum  = (float*)(smc + SOFF_SUM);
    float* sInv  = (float*)(smc + SOFF_INV);
    float*  sE  = (float*)(smc + SOFF_E);
    __half* sPh = (__half*)(smc + SOFF_K);
    const uint32_t uKh = smem_u32(smc) + SOFF_K;
    const uint32_t uQh = smem_u32(smc) + SOFF_U;
    const uint32_t uE  = smem_u32(smc) + SOFF_E;
    const uint32_t uV  = smem_u32(smc) + SOFF_V;
    const uint32_t uP  = smem_u32(smc) + SOFF_K;

    const int tid  = threadIdx.x;
    const int lane = tid & 31;
    const int wid  = tid >> 5;
    const int b  = blockIdx.z;
    const int h  = blockIdx.y;
    const int i0 = blockIdx.x * 64;
    const size_t bh = (size_t)(b * HH + h);
    const size_t wbase = (size_t)BB * SS * DD + (bh * SS + i0) * SS;

    const int wm = wid >> 2;        // 0..1
    const int wn = wid & 3;         // 0..3
    const int lr16 = lane & 15;
    const int lkb = (lane >> 4) * 8;
    const int grow = lane >> 2;
    const int gcol = (lane & 3) * 2;

    if (tid < 64) sSum[tid] = 0.f;
    // Prologue: K tile (hi+lo) + Q chunk 0 (hi) in one drain
#pragma unroll
    for (int it = 0; it < 4; it++) {
        int p = tid + it * 256;
        int row = p >> 4, seg = p & 15;
        size_t go = (bh * SS + i0 + row) * DH + seg * 8;
        uint32_t so = (uint32_t)(row * KP + seg * 8) * 2;
        cpa16cg(uKh + so, g_kh + go);
        cpa16cg(uKh + (SOFF_KL - SOFF_K) + so, g_kl + go);
    }
#pragma unroll
    for (int it = 0; it < 8; it++) {
        int p = tid + it * 256;
        int row = p >> 4, seg = p & 15;
        cpa16cg(uQh + (uint32_t)(row * KP + seg * 8) * 2,
                g_qh + (bh * SS + row) * DH + seg * 8);
    }
    CP_COMMIT();
    for (int j = tid; j < SS; j += 256) sMask[j] = mask[b * SS + j];

    // ================= Phase 1: e = exp(score) -> global; sums in regs ======
    float psum[2][2] = {{0.f, 0.f}, {0.f, 0.f}};
#pragma unroll 1
    for (int ct = 0; ct < 8; ct++) {
        CP_WAIT(0);
        __syncthreads();

        float acc[2][4][4];
#pragma unroll
        for (int i = 0; i < 2; i++)
#pragma unroll
            for (int j = 0; j < 4; j++)
#pragma unroll
                for (int cc = 0; cc < 4; cc++) acc[i][j][cc] = 0.f;

#pragma unroll
        for (int ks = 0; ks < 8; ks++) {
            const int ke = ks * 16 + lkb;
            uint32_t kh[2][4], kl[2][4], qh[2][4];
#pragma unroll
            for (int mi = 0; mi < 2; mi++) {
                uint32_t ad = uKh + (uint32_t)((wm * 32 + mi * 16 + lr16) * KP + ke) * 2;
                ldsm_x4(kh[mi], ad);
                ldsm_x4(kl[mi], ad + (SOFF_KL - SOFF_K));
            }
#pragma unroll
            for (int nb = 0; nb < 2; nb++)
                ldsm_x4(qh[nb], uQh + (uint32_t)((wn * 32 + nb * 16 + lr16) * KP + ke) * 2);
            // pass 1: Kh·Qh
#pragma unroll
            for (int mi = 0; mi < 2; mi++)
#pragma unroll
                for (int nb = 0; nb < 2; nb++) {
                    mma_fp16(acc[mi][nb*2+0], kh[mi], qh[nb][0], qh[nb][2]);
                    mma_fp16(acc[mi][nb*2+1], kh[mi], qh[nb][1], qh[nb][3]);
                }
            // pass 2: Kl·Qh
#pragma unroll
            for (int mi = 0; mi < 2; mi++)
#pragma unroll
                for (int nb = 0; nb < 2; nb++) {
                    mma_fp16(acc[mi][nb*2+0], kl[mi], qh[nb][0], qh[nb][2]);
                    mma_fp16(acc[mi][nb*2+1], kl[mi], qh[nb][1], qh[nb][3]);
                }
        }

#pragma unroll
        for (int mi = 0; mi < 2; mi++)
#pragma unroll
            for (int nj = 0; nj < 4; nj++) {
                int jg = ct * 128 + wn * 32 + (nj >> 1) * 16 + (nj & 1) * 8 + gcol;
                bool m0 = sMask[jg] != 0, m1 = sMask[jg + 1] != 0;
                int ir = wm * 32 + mi * 16 + grow;
                const float* a4 = acc[mi][nj];
                float2 r0, r1;
                r0.x = m0 ? __expf(a4[0] * SCALE) : 1e-37f;
                r0.y = m1 ? __expf(a4[1] * SCALE) : 1e-37f;
                r1.x = m0 ? __expf(a4[2] * SCALE) : 1e-37f;
                r1.y = m1 ? __expf(a4[3] * SCALE) : 1e-37f;
                psum[mi][0] += r0.x + r0.y;
                psum[mi][1] += r1.x + r1.y;
                *(float2*)&out[wbase + (size_t)ir * SS + jg]       = r0;
                *(float2*)&out[wbase + (size_t)(ir + 8) * SS + jg] = r1;
            }
        __syncthreads();

        if (ct + 1 < 8) {
#pragma unroll
            for (int it = 0; it < 8; it++) {
                int p = tid + it * 256;
                int row = p >> 4, seg = p & 15;
                cpa16cg(uQh + (uint32_t)(row * KP + seg * 8) * 2,
                        g_qh + (bh * SS + (ct + 1) * 128 + row) * DH + seg * 8);
            }
            CP_COMMIT();
        }
    }

    // row-sum reduction -> sInv
#pragma unroll
    for (int mi = 0; mi < 2; mi++)
#pragma unroll
        for (int hf = 0; hf < 2; hf++) {
            psum[mi][hf] += __shfl_xor_sync(~0u, psum[mi][hf], 1);
            psum[mi][hf] += __shfl_xor_sync(~0u, psum[mi][hf], 2);
        }
    if ((lane & 3) == 0) {
#pragma unroll
        for (int mi = 0; mi < 2; mi++) {
            atomicAdd(&sSum[wm * 32 + mi * 16 + grow],     psum[mi][0]);
            atomicAdd(&sSum[wm * 32 + mi * 16 + grow + 8], psum[mi][1]);
        }
    }
    __syncthreads();
    if (tid < 64) sInv[tid] = 1.0f / sSum[tid];
    __threadfence_block();
    __syncthreads();

    // ================= Phase 3: pipelined normalize + PV (fp16) =============
    float racc[2][4][4];
#pragma unroll
    for (int i = 0; i < 2; i++)
#pragma unroll
        for (int j = 0; j < 4; j++)
#pragma unroll
            for (int cc = 0; cc < 4; cc++) racc[i][j][cc] = 0.f;

    const int crow = tid >> 2;          // 0..63
    const int cq   = tid & 3;

    // prologue: issue E0, V0 in separate groups
#pragma unroll
    for (int it = 0; it < 8; it++) {
        int p = tid + it * 256;
        int row = p >> 5, seg = p & 31;
        cpa16cg(uE + (uint32_t)(row * EPITCH + seg * 4) * 4,
                out + wbase + (size_t)row * SS + seg * 4);
    }
    CP_COMMIT();
#pragma unroll
    for (int it = 0; it < 8; it++) {
        int p = tid + it * 256;
        int row = p >> 4, seg = p & 15;
        cpa16cg(uV + (uint32_t)(row * VPITCH + seg * 8) * 2,
                g_vth + (bh * DH + row) * SS + seg * 8);
    }
    CP_COMMIT();

#pragma unroll 1
    for (int jc = 0; jc < 8; jc++) {
        CP_WAIT(1);                 // E_jc ready
        __syncthreads();

        // normalize from SMEM: w -> global, fp16 w -> P tile
        {
            float inv = sInv[crow];
            const float* erow = sE + crow * EPITCH;
            float* wrow = out + wbase + (size_t)crow * SS + jc * 128;
#pragma unroll
            for (int k = 0; k < 8; k++) {
                int col = cq * 4 + k * 16;
                float4 e4 = *(const float4*)&erow[col];
                float4 w4;
                w4.x = e4.x * inv; w4.y = e4.y * inv;
                w4.z = e4.z * inv; w4.w = e4.w * inv;
                *(float4*)&wrow[col] = w4;
                union { uint2 u; __half2 h2[2]; } pk;
                pk.h2[0] = __floats2half2_rn(w4.x, w4.y);
                pk.h2[1] = __floats2half2_rn(w4.z, w4.w);
                *(uint2*)&sPh[crow * PPITCH + col] = pk.u;
            }
        }
        __syncthreads();            // E consumed; P complete

        if (jc + 1 < 8) {
#pragma unroll
            for (int it = 0; it < 8; it++) {
                int p = tid + it * 256;
                int row = p >> 5, seg = p & 31;
                cpa16cg(uE + (uint32_t)(row * EPITCH + seg * 4) * 4,
                        out + wbase + (size_t)row * SS + (jc + 1) * 128 + seg * 4);
            }
            CP_COMMIT();
        }

        CP_WAIT(1);                 // V_jc ready
        __syncthreads();

#pragma unroll
        for (int ks = 0; ks < 8; ks++) {
            const int ke = ks * 16 + lkb;
            uint32_t pa[2][4], vh[2][4];
#pragma unroll
            for (int mi = 0; mi < 2; mi++)
                ldsm_x4(pa[mi], uP + (uint32_t)((wm * 32 + mi * 16 + lr16) * PPITCH + ke) * 2);
#pragma unroll
            for (int nb = 0; nb < 2; nb++)
                ldsm_x4(vh[nb], uV + (uint32_t)((wn * 32 + nb * 16 + lr16) * VPITCH + ke) * 2);
#pragma unroll
            for (int mi = 0; mi < 2; mi++)
#pragma unroll
                for (int nb = 0; nb < 2; nb++) {
                    mma_fp16(racc[mi][nb*2+0], pa[mi], vh[nb][0], vh[nb][2]);
                    mma_fp16(racc[mi][nb*2+1], pa[mi], vh[nb][1], vh[nb][3]);
                }
        }
        __syncthreads();            // V consumed

        if (jc + 1 < 8) {
#pragma unroll
            for (int it = 0; it < 8; it++) {
                int p = tid + it * 256;
                int row = p >> 4, seg = p & 15;
                cpa16cg(uV + (uint32_t)(row * VPITCH + seg * 8) * 2,
                        g_vth + (bh * DH + row) * SS + (jc + 1) * 128 + seg * 8);
            }
            CP_COMMIT();
        }
    }

    // epilogue: out = m_feats + R (P normalized)
#pragma unroll
    for (int mi = 0; mi < 2; mi++)
#pragma unroll
        for (int nj = 0; nj < 4; nj++) {
            int d = wn * 32 + (nj >> 1) * 16 + (nj & 1) * 8 + gcol;
            int ir = wm * 32 + mi * 16 + grow;
            const float* a4 = racc[mi][nj];
            size_t o0 = ((size_t)b * SS + i0 + ir) * DD + h * DH + d;
            float2 mf0 = *(const float2*)&m_feats[o0];
            *(float2*)&out[o0] = make_float2(mf0.x + a4[0], mf0.y + a4[1]);
            size_t o1 = o0 + (size_t)8 * DD;
            float2 mf1 = *(const float2*)&m_feats[o1];
            *(float2*)&out[o1] = make_float2(mf1.x + a4[2], mf1.y + a4[3]);
        }
}

// ---------------------------------------------------------------------------
extern "C" void kernel_launch(void* const* d_in, const int* in_sizes, int n_in,
                              void* d_out, int out_size)
{
    const float* m_feats = (const float*)d_in[0];
    const int*   mask    = (const int*)d_in[1];
    const float* c_w     = (const float*)d_in[2];
    const float* c_b     = (const float*)d_in[3];
    const float* v_w     = (const float*)d_in[4];
    const float* v_b     = (const float*)d_in[5];
    float* out = (float*)d_out;

    conv_kernel<<<(A_I4 + W_I4 + 255) / 256, 256>>>(m_feats, c_w, v_w);

    cudaFuncSetAttribute(gemm_kernel,
                         cudaFuncAttributeMaxDynamicSharedMemorySize, GEMM_SMEM_B);
    dim3 gG(NN / 128, BB * SS / 128);
    gemm_kernel<<<gG, 256, GEMM_SMEM_B>>>(c_b, v_b);

    cudaFuncSetAttribute(attn_kernel,
                         cudaFuncAttributeMaxDynamicSharedMemorySize, ATTN_SMEM);
    dim3 gB(SS / 64, HH, BB);
    attn_kernel<<<gB, 256, ATTN_SMEM>>>(m_feats, mask, out);
}

// round 16
// speedup vs baseline: 1.6577x; 1.2221x over previous
#include <cuda_runtime.h>
#include <cuda_fp16.h>
#include <cstdint>

#define BB 8
#define SS 1024
#define DD 1024
#define HH 8
#define DH 128
#define NN 3072
#define SCALE 0.08838834764831845f   // 1/sqrt(128)

// ---------------------------------------------------------------------------
// Device scratch
// ---------------------------------------------------------------------------
__device__ __half g_kh[BB*HH*SS*DH];   // K hi  [bh][s][d]
__device__ __half g_kl[BB*HH*SS*DH];   // K lo
__device__ __half g_qh[BB*HH*SS*DH];   // Q hi  [bh][s][d]
__device__ __half g_vth[BB*HH*DH*SS];  // V^T hi [bh][d][s]
__device__ __half g_Ah[BB*SS*DD];      // m_feats fp16
__device__ __half g_Wh[NN*DD];         // [v_w ; c_w] fp16

// ---------------------------------------------------------------------------
// Conversion kernel: A -> fp16; W -> fp16
// ---------------------------------------------------------------------------
#define A_I4 (BB*SS*DD/4)
#define W_I4 (NN*DD/4)

__global__ __launch_bounds__(256) void conv_kernel(const float* __restrict__ A,
                                                   const float* __restrict__ c_w,
                                                   const float* __restrict__ v_w) {
    int i4 = blockIdx.x * 256 + threadIdx.x;
    if (i4 < A_I4) {
        float4 v = ((const float4*)A)[i4];
        ((__half2*)g_Ah)[i4*2]   = __floats2half2_rn(v.x, v.y);
        ((__half2*)g_Ah)[i4*2+1] = __floats2half2_rn(v.z, v.w);
    } else {
        int w4 = i4 - A_I4;
        if (w4 >= W_I4) return;
        int e = w4 * 4;
        int n = e >> 10, k = e & 1023;
        const float* src = (n < DD) ? (v_w + (size_t)n * DD + k)
                                    : (c_w + (size_t)(n - DD) * DD + k);
        float4 v = *(const float4*)src;
        ((__half2*)g_Wh)[w4*2]   = __floats2half2_rn(v.x, v.y);
        ((__half2*)g_Wh)[w4*2+1] = __floats2half2_rn(v.z, v.w);
    }
}

// ---------------------------------------------------------------------------
// helpers
// ---------------------------------------------------------------------------
__device__ __forceinline__ uint32_t smem_u32(const void* p) {
    uint32_t a;
    asm("{ .reg .u64 t; cvta.to.shared.u64 t, %1; cvt.u32.u64 %0, t; }" : "=r"(a) : "l"(p));
    return a;
}
__device__ __forceinline__ void ldsm_x4(uint32_t* r, uint32_t addr) {
    asm volatile("ldmatrix.sync.aligned.m8n8.x4.shared.b16 {%0,%1,%2,%3}, [%4];"
                 : "=r"(r[0]), "=r"(r[1]), "=r"(r[2]), "=r"(r[3]) : "r"(addr));
}
__device__ __forceinline__ void mma_fp16(float* c, const uint32_t* a, uint32_t b0, uint32_t b1) {
    asm volatile(
        "mma.sync.aligned.m16n8k16.row.col.f32.f16.f16.f32 "
        "{%0,%1,%2,%3}, {%4,%5,%6,%7}, {%8,%9}, {%0,%1,%2,%3};"
        : "+f"(c[0]), "+f"(c[1]), "+f"(c[2]), "+f"(c[3])
        : "r"(a[0]), "r"(a[1]), "r"(a[2]), "r"(a[3]), "r"(b0), "r"(b1));
}
__device__ __forceinline__ void cpa16ca(uint32_t dst, const void* src) {
    asm volatile("cp.async.ca.shared.global [%0], [%1], 16;" :: "r"(dst), "l"(src));
}
__device__ __forceinline__ void cpa16cg(uint32_t dst, const void* src) {
    asm volatile("cp.async.cg.shared.global [%0], [%1], 16;" :: "r"(dst), "l"(src));
}
#define CP_COMMIT() asm volatile("cp.async.commit_group;")
#define CP_WAIT(n)  asm volatile("cp.async.wait_group %0;" :: "n"(n))

__device__ __forceinline__ void store_hilo_h(__half* hh_, __half* hl_,
                                             size_t off, float x0, float x1) {
    __half h0 = __float2half_rn(x0), h1 = __float2half_rn(x1);
    *(__half2*)(hh_ + off) = __halves2half2(h0, h1);
    *(__half2*)(hl_ + off) = __floats2half2_rn(x0 - __half2float(h0),
                                               x1 - __half2float(h1));
}

// ---------------------------------------------------------------------------
// Projection GEMM: plain fp16 1-pass Ah·Wh, all outputs. occ 2.
// ---------------------------------------------------------------------------
#define KC 32
#define ROWP 40
#define BUF_E (128*ROWP)
#define OFF_AH 0
#define OFF_BH BUF_E
#define GEMM_SMEM_B (4*BUF_E*2 + 512)   // 41472 bytes

__device__ __forceinline__ void issue_op(uint32_t sdst, const __half* g,
                                         int tid, int k0) {
#pragma unroll
    for (int j = 0; j < 2; j++) {
        int u = tid + j * 256;
        int row = u >> 2, seg = u & 3;
        cpa16ca(sdst + (uint32_t)(row * ROWP + seg * 8) * 2,
                g + (size_t)row * DD + k0 + seg * 8);
    }
}

__global__ __launch_bounds__(256, 2) void gemm_kernel(const float* __restrict__ c_b,
                                                      const float* __restrict__ v_b) {
    extern __shared__ __half sm[];
    float* sBias = (float*)(sm + 4 * BUF_E);
    const uint32_t sbase = smem_u32(sm);

    const int tid  = threadIdx.x;
    const int lane = tid & 31;
    const int wid  = tid >> 5;
    const int wm   = wid >> 1;
    const int wn   = wid & 1;
    const int n0   = blockIdx.x * 128;
    const int m0   = blockIdx.y * 128;
    const int kind = n0 >> 10;

    const __half* Ah = g_Ah + (size_t)m0 * DD;
    const __half* Bh = g_Wh + (size_t)n0 * DD;

    const float* bp = (n0 < DD) ? (v_b + n0) : (c_b + (n0 - DD));
    if (tid < 128) sBias[tid] = bp[tid];

    float acc[2][8][4];
#pragma unroll
    for (int i = 0; i < 2; i++)
#pragma unroll
        for (int j = 0; j < 8; j++)
#pragma unroll
            for (int c = 0; c < 4; c++) acc[i][j][c] = 0.f;

    const int lrow_a = wm * 32 + (lane & 15);
    const int lrow_b0 = wn * 64 + (lane & 15);
    const int lk = ((lane >> 4) & 1) * 8;

    {
        issue_op(sbase + OFF_AH * 2, Ah, tid, 0);
        issue_op(sbase + OFF_BH * 2, Bh, tid, 0);
        CP_COMMIT();
    }

#pragma unroll 1
    for (int c = 0; c < DD / KC; c++) {
        const int cur = c & 1;
        if (c + 1 < DD / KC) {
            uint32_t bu = sbase + (uint32_t)((cur ^ 1) * 2 * BUF_E) * 2;
            int k0 = (c + 1) * KC;
            issue_op(bu + OFF_AH * 2, Ah, tid, k0);
            issue_op(bu + OFF_BH * 2, Bh, tid, k0);
            CP_COMMIT();
            CP_WAIT(1);
        } else {
            CP_WAIT(0);
        }
        __syncthreads();

        const __half* base = sm + cur * 2 * BUF_E;
#pragma unroll
        for (int kk = 0; kk < 2; kk++) {
            const int ke = kk * 16 + lk;
            uint32_t ah[2][4], bh[4][4];
#pragma unroll
            for (int mi = 0; mi < 2; mi++)
                ldsm_x4(ah[mi], smem_u32(base + OFF_AH + (lrow_a + mi * 16) * ROWP + ke));
#pragma unroll
            for (int nb = 0; nb < 4; nb++)
                ldsm_x4(bh[nb], smem_u32(base + OFF_BH + (lrow_b0 + nb * 16) * ROWP + ke));
#pragma unroll
            for (int mi = 0; mi < 2; mi++)
#pragma unroll
                for (int nb = 0; nb < 4; nb++) {
                    mma_fp16(acc[mi][nb*2+0], ah[mi], bh[nb][0], bh[nb][2]);
                    mma_fp16(acc[mi][nb*2+1], ah[mi], bh[nb][1], bh[nb][3]);
                }
        }
        __syncthreads();
    }

    const int h = (n0 >> 7) & 7;
    const int b_ = m0 >> 10;
    const int g = lane >> 2;
    const int tc = (lane & 3) * 2;
    const size_t bh_off = (size_t)(b_ * HH + h);

#pragma unroll
    for (int mi = 0; mi < 2; mi++) {
#pragma unroll
        for (int nj = 0; nj < 8; nj++) {
            const float* a4 = acc[mi][nj];
            int d = wn * 64 + nj * 8 + tc;
            float bx = sBias[d], by = sBias[d + 1];
            int s0 = (m0 + wm * 32 + mi * 16 + g) & 1023;
            float x0 = a4[0] + bx, x1 = a4[1] + by;
            float x2 = a4[2] + bx, x3 = a4[3] + by;
            if (kind == 2) {
                __half* dst = g_vth + bh_off * DH * SS;
                dst[(size_t)d * SS + s0]           = __float2half_rn(x0);
                dst[(size_t)(d + 1) * SS + s0]     = __float2half_rn(x1);
                dst[(size_t)d * SS + s0 + 8]       = __float2half_rn(x2);
                dst[(size_t)(d + 1) * SS + s0 + 8] = __float2half_rn(x3);
            } else if (kind == 0) {
                size_t base_off = (bh_off * SS + s0) * DH + d;
                store_hilo_h(g_kh, g_kl, base_off, x0, x1);
                store_hilo_h(g_kh, g_kl, base_off + 8 * DH, x2, x3);
            } else {
                size_t base_off = (bh_off * SS + s0) * DH + d;
                *(__half2*)(g_qh + base_off)          = __floats2half2_rn(x0, x1);
                *(__half2*)(g_qh + base_off + 8 * DH) = __floats2half2_rn(x2, x3);
            }
        }
    }
}

// ---------------------------------------------------------------------------
// Monolithic attention, TI=64, occ 2. fp16 2-pass scores ((Kh+Kl)·Qh).
// ---------------------------------------------------------------------------
#define KP 136
#define EPITCH 132                     // floats
#define VPITCH 136
#define PPITCH 136
#define SOFF_K    0                    // P1: Kh(17408)+Kl(17408) | P3: P(17408)
#define SOFF_KL   17408
#define SOFF_U    34816                // P1: Qh(17408) | P3: E(33792)+V(34816)
#define SOFF_E    SOFF_U
#define SOFF_V    (SOFF_U + 33792)     // 68608
#define SOFF_MASK 103424
#define SOFF_SUM  107520               // 64 floats
#define SOFF_INV  107776               // 64 floats
#define ATTN_SMEM 108032

__global__ __launch_bounds__(256, 2) void attn_kernel(
    const float* __restrict__ m_feats,
    const int*   __restrict__ mask,
    float* __restrict__ out)
{
    extern __shared__ char smc[];
    int*   sMask = (int*)(smc + SOFF_MASK);
    float* sSum  = (float*)(smc + SOFF_SUM);
    float* sInv  = (float*)(smc + SOFF_INV);
    float*  sE  = (float*)(smc + SOFF_E);
    __half* sPh = (__half*)(smc + SOFF_K);
    const uint32_t uKh = smem_u32(smc) + SOFF_K;
    const uint32_t uQh = smem_u32(smc) + SOFF_U;
    const uint32_t uE  = smem_u32(smc) + SOFF_E;
    const uint32_t uV  = smem_u32(smc) + SOFF_V;
    const uint32_t uP  = smem_u32(smc) + SOFF_K;

    const int tid  = threadIdx.x;
    const int lane = tid & 31;
    const int wid  = tid >> 5;
    const int b  = blockIdx.z;
    const int h  = blockIdx.y;
    const int i0 = blockIdx.x * 64;
    const size_t bh = (size_t)(b * HH + h);
    const size_t wbase = (size_t)BB * SS * DD + (bh * SS + i0) * SS;

    const int wm = wid >> 2;        // 0..1
    const int wn = wid & 3;         // 0..3
    const int lr16 = lane & 15;
    const int lkb = (lane >> 4) * 8;
    const int grow = lane >> 2;
    const int gcol = (lane & 3) * 2;

    if (tid < 64) sSum[tid] = 0.f;
#pragma unroll
    for (int it = 0; it < 4; it++) {
        int p = tid + it * 256;
        int row = p >> 4, seg = p & 15;
        size_t go = (bh * SS + i0 + row) * DH + seg * 8;
        uint32_t so = (uint32_t)(row * KP + seg * 8) * 2;
        cpa16cg(uKh + so, g_kh + go);
        cpa16cg(uKh + (SOFF_KL - SOFF_K) + so, g_kl + go);
    }
#pragma unroll
    for (int it = 0; it < 8; it++) {
        int p = tid + it * 256;
        int row = p >> 4, seg = p & 15;
        cpa16cg(uQh + (uint32_t)(row * KP + seg * 8) * 2,
                g_qh + (bh * SS + row) * DH + seg * 8);
    }
    CP_COMMIT();
    for (int j = tid; j < SS; j += 256) sMask[j] = mask[b * SS + j];

    // ================= Phase 1: e = exp(score) -> global; sums in regs ======
    float psum[2][2] = {{0.f, 0.f}, {0.f, 0.f}};
#pragma unroll 1
    for (int ct = 0; ct < 8; ct++) {
        CP_WAIT(0);
        __syncthreads();

        float acc[2][4][4];
#pragma unroll
        for (int i = 0; i < 2; i++)
#pragma unroll
            for (int j = 0; j < 4; j++)
#pragma unroll
                for (int cc = 0; cc < 4; cc++) acc[i][j][cc] = 0.f;

#pragma unroll
        for (int ks = 0; ks < 8; ks++) {
            const int ke = ks * 16 + lkb;
            uint32_t kh[2][4], kl[2][4], qh[2][4];
#pragma unroll
            for (int mi = 0; mi < 2; mi++) {
                uint32_t ad = uKh + (uint32_t)((wm * 32 + mi * 16 + lr16) * KP + ke) * 2;
                ldsm_x4(kh[mi], ad);
                ldsm_x4(kl[mi], ad + (SOFF_KL - SOFF_K));
            }
#pragma unroll
            for (int nb = 0; nb < 2; nb++)
                ldsm_x4(qh[nb], uQh + (uint32_t)((wn * 32 + nb * 16 + lr16) * KP + ke) * 2);
#pragma unroll
            for (int mi = 0; mi < 2; mi++)
#pragma unroll
                for (int nb = 0; nb < 2; nb++) {
                    mma_fp16(acc[mi][nb*2+0], kh[mi], qh[nb][0], qh[nb][2]);
                    mma_fp16(acc[mi][nb*2+1], kh[mi], qh[nb][1], qh[nb][3]);
                }
#pragma unroll
            for (int mi = 0; mi < 2; mi++)
#pragma unroll
                for (int nb = 0; nb < 2; nb++) {
                    mma_fp16(acc[mi][nb*2+0], kl[mi], qh[nb][0], qh[nb][2]);
                    mma_fp16(acc[mi][nb*2+1], kl[mi], qh[nb][1], qh[nb][3]);
                }
        }

#pragma unroll
        for (int mi = 0; mi < 2; mi++)
#pragma unroll
            for (int nj = 0; nj < 4; nj++) {
                int jg = ct * 128 + wn * 32 + (nj >> 1) * 16 + (nj & 1) * 8 + gcol;
                bool m0 = sMask[jg] != 0, m1 = sMask[jg + 1] != 0;
                int ir = wm * 32 + mi * 16 + grow;
                const float* a4 = acc[mi][nj];
                float2 r0, r1;
                r0.x = m0 ? __expf(a4[0] * SCALE) : 1e-37f;
                r0.y = m1 ? __expf(a4[1] * SCALE) : 1e-37f;
                r1.x = m0 ? __expf(a4[2] * SCALE) : 1e-37f;
                r1.y = m1 ? __expf(a4[3] * SCALE) : 1e-37f;
                psum[mi][0] += r0.x + r0.y;
                psum[mi][1] += r1.x + r1.y;
                *(float2*)&out[wbase + (size_t)ir * SS + jg]       = r0;
                *(float2*)&out[wbase + (size_t)(ir + 8) * SS + jg] = r1;
            }
        __syncthreads();

        if (ct + 1 < 8) {
#pragma unroll
            for (int it = 0; it < 8; it++) {
                int p = tid + it * 256;
                int row = p >> 4, seg = p & 15;
                cpa16cg(uQh + (uint32_t)(row * KP + seg * 8) * 2,
                        g_qh + (bh * SS + (ct + 1) * 128 + row) * DH + seg * 8);
            }
            CP_COMMIT();
        }
    }

    // row-sum reduction -> sInv
#pragma unroll
    for (int mi = 0; mi < 2; mi++)
#pragma unroll
        for (int hf = 0; hf < 2; hf++) {
            psum[mi][hf] += __shfl_xor_sync(~0u, psum[mi][hf], 1);
            psum[mi][hf] += __shfl_xor_sync(~0u, psum[mi][hf], 2);
        }
    if ((lane & 3) == 0) {
#pragma unroll
        for (int mi = 0; mi < 2; mi++) {
            atomicAdd(&sSum[wm * 32 + mi * 16 + grow],     psum[mi][0]);
            atomicAdd(&sSum[wm * 32 + mi * 16 + grow + 8], psum[mi][1]);
        }
    }
    __syncthreads();
    if (tid < 64) sInv[tid] = 1.0f / sSum[tid];
    __threadfence_block();
    __syncthreads();

    // ================= Phase 3: pipelined normalize + PV (fp16) =============
    float racc[2][4][4];
#pragma unroll
    for (int i = 0; i < 2; i++)
#pragma unroll
        for (int j = 0; j < 4; j++)
#pragma unroll
            for (int cc = 0; cc < 4; cc++) racc[i][j][cc] = 0.f;

    const int crow = tid >> 2;          // 0..63
    const int cq   = tid & 3;

#pragma unroll
    for (int it = 0; it < 8; it++) {
        int p = tid + it * 256;
        int row = p >> 5, seg = p & 31;
        cpa16cg(uE + (uint32_t)(row * EPITCH + seg * 4) * 4,
                out + wbase + (size_t)row * SS + seg * 4);
    }
    CP_COMMIT();
#pragma unroll
    for (int it = 0; it < 8; it++) {
        int p = tid + it * 256;
        int row = p >> 4, seg = p & 15;
        cpa16cg(uV + (uint32_t)(row * VPITCH + seg * 8) * 2,
                g_vth + (bh * DH + row) * SS + seg * 8);
    }
    CP_COMMIT();

#pragma unroll 1
    for (int jc = 0; jc < 8; jc++) {
        CP_WAIT(1);                 // E_jc ready
        __syncthreads();

        {
            float inv = sInv[crow];
            const float* erow = sE + crow * EPITCH;
            float* wrow = out + wbase + (size_t)crow * SS + jc * 128;
#pragma unroll
            for (int k = 0; k < 8; k++) {
                int col = cq * 4 + k * 16;
                float4 e4 = *(const float4*)&erow[col];
                float4 w4;
                w4.x = e4.x * inv; w4.y = e4.y * inv;
                w4.z = e4.z * inv; w4.w = e4.w * inv;
                *(float4*)&wrow[col] = w4;
                union { uint2 u; __half2 h2[2]; } pk;
                pk.h2[0] = __floats2half2_rn(w4.x, w4.y);
                pk.h2[1] = __floats2half2_rn(w4.z, w4.w);
                *(uint2*)&sPh[crow * PPITCH + col] = pk.u;
            }
        }
        __syncthreads();

        if (jc + 1 < 8) {
#pragma unroll
            for (int it = 0; it < 8; it++) {
                int p = tid + it * 256;
                int row = p >> 5, seg = p & 31;
                cpa16cg(uE + (uint32_t)(row * EPITCH + seg * 4) * 4,
                        out + wbase + (size_t)row * SS + (jc + 1) * 128 + seg * 4);
            }
            CP_COMMIT();
        }

        CP_WAIT(1);                 // V_jc ready
        __syncthreads();

#pragma unroll
        for (int ks = 0; ks < 8; ks++) {
            const int ke = ks * 16 + lkb;
            uint32_t pa[2][4], vh[2][4];
#pragma unroll
            for (int mi = 0; mi < 2; mi++)
                ldsm_x4(pa[mi], uP + (uint32_t)((wm * 32 + mi * 16 + lr16) * PPITCH + ke) * 2);
#pragma unroll
            for (int nb = 0; nb < 2; nb++)
                ldsm_x4(vh[nb], uV + (uint32_t)((wn * 32 + nb * 16 + lr16) * VPITCH + ke) * 2);
#pragma unroll
            for (int mi = 0; mi < 2; mi++)
#pragma unroll
                for (int nb = 0; nb < 2; nb++) {
                    mma_fp16(racc[mi][nb*2+0], pa[mi], vh[nb][0], vh[nb][2]);
                    mma_fp16(racc[mi][nb*2+1], pa[mi], vh[nb][1], vh[nb][3]);
                }
        }
        __syncthreads();

        if (jc + 1 < 8) {
#pragma unroll
            for (int it = 0; it < 8; it++) {
                int p = tid + it * 256;
                int row = p >> 4, seg = p & 15;
                cpa16cg(uV + (uint32_t)(row * VPITCH + seg * 8) * 2,
                        g_vth + (bh * DH + row) * SS + (jc + 1) * 128 + seg * 8);
            }
            CP_COMMIT();
        }
    }

    // epilogue: out = m_feats + R
#pragma unroll
    for (int mi = 0; mi < 2; mi++)
#pragma unroll
        for (int nj = 0; nj < 4; nj++) {
            int d = wn * 32 + (nj >> 1) * 16 + (nj & 1) * 8 + gcol;
            int ir = wm * 32 + mi * 16 + grow;
            const float* a4 = racc[mi][nj];
            size_t o0 = ((size_t)b * SS + i0 + ir) * DD + h * DH + d;
            float2 mf0 = *(const float2*)&m_feats[o0];
            *(float2*)&out[o0] = make_float2(mf0.x + a4[0], mf0.y + a4[1]);
            size_t o1 = o0 + (size_t)8 * DD;
            float2 mf1 = *(const float2*)&m_feats[o1];
            *(float2*)&out[o1] = make_float2(mf1.x + a4[2], mf1.y + a4[3]);
        }
}

// ---------------------------------------------------------------------------
extern "C" void kernel_launch(void* const* d_in, const int* in_sizes, int n_in,
                              void* d_out, int out_size)
{
    const float* m_feats = (const float*)d_in[0];
    const int*   mask    = (const int*)d_in[1];
    const float* c_w     = (const float*)d_in[2];
    const float* c_b     = (const float*)d_in[3];
    const float* v_w     = (const float*)d_in[4];
    const float* v_b     = (const float*)d_in[5];
    float* out = (float*)d_out;

    conv_kernel<<<(A_I4 + W_I4 + 255) / 256, 256>>>(m_feats, c_w, v_w);

    cudaFuncSetAttribute(gemm_kernel,
                         cudaFuncAttributeMaxDynamicSharedMemorySize, GEMM_SMEM_B);
    dim3 gG(NN / 128, BB * SS / 128);
    gemm_kernel<<<gG, 256, GEMM_SMEM_B>>>(c_b, v_b);

    cudaFuncSetAttribute(attn_kernel,
                         cudaFuncAttributeMaxDynamicSharedMemorySize, ATTN_SMEM);
    dim3 gB(SS / 64, HH, BB);
    attn_kernel<<<gB, 256, ATTN_SMEM>>>(m_feats, mask, out);
}

// round 17
// speedup vs baseline: 1.7491x; 1.0551x over previous
#include <cuda_runtime.h>
#include <cuda_fp16.h>
#include <cstdint>

#define BB 8
#define SS 1024
#define DD 1024
#define HH 8
#define DH 128
#define NN 3072
#define SCALE 0.08838834764831845f   // 1/sqrt(128)

// ---------------------------------------------------------------------------
// Device scratch (all fp16 single precision now)
// ---------------------------------------------------------------------------
__device__ __half g_kh[BB*HH*SS*DH];   // K  [bh][s][d]
__device__ __half g_qh[BB*HH*SS*DH];   // Q  [bh][s][d]
__device__ __half g_vth[BB*HH*DH*SS];  // V^T [bh][d][s]
__device__ __half g_Ah[BB*SS*DD];      // m_feats fp16
__device__ __half g_Wh[NN*DD];         // [v_w ; c_w] fp16

// ---------------------------------------------------------------------------
// Conversion kernel
// ---------------------------------------------------------------------------
#define A_I4 (BB*SS*DD/4)
#define W_I4 (NN*DD/4)

__global__ __launch_bounds__(256) void conv_kernel(const float* __restrict__ A,
                                                   const float* __restrict__ c_w,
                                                   const float* __restrict__ v_w) {
    int i4 = blockIdx.x * 256 + threadIdx.x;
    if (i4 < A_I4) {
        float4 v = ((const float4*)A)[i4];
        ((__half2*)g_Ah)[i4*2]   = __floats2half2_rn(v.x, v.y);
        ((__half2*)g_Ah)[i4*2+1] = __floats2half2_rn(v.z, v.w);
    } else {
        int w4 = i4 - A_I4;
        if (w4 >= W_I4) return;
        int e = w4 * 4;
        int n = e >> 10, k = e & 1023;
        const float* src = (n < DD) ? (v_w + (size_t)n * DD + k)
                                    : (c_w + (size_t)(n - DD) * DD + k);
        float4 v = *(const float4*)src;
        ((__half2*)g_Wh)[w4*2]   = __floats2half2_rn(v.x, v.y);
        ((__half2*)g_Wh)[w4*2+1] = __floats2half2_rn(v.z, v.w);
    }
}

// ---------------------------------------------------------------------------
// helpers
// ---------------------------------------------------------------------------
__device__ __forceinline__ uint32_t smem_u32(const void* p) {
    uint32_t a;
    asm("{ .reg .u64 t; cvta.to.shared.u64 t, %1; cvt.u32.u64 %0, t; }" : "=r"(a) : "l"(p));
    return a;
}
__device__ __forceinline__ void ldsm_x4(uint32_t* r, uint32_t addr) {
    asm volatile("ldmatrix.sync.aligned.m8n8.x4.shared.b16 {%0,%1,%2,%3}, [%4];"
                 : "=r"(r[0]), "=r"(r[1]), "=r"(r[2]), "=r"(r[3]) : "r"(addr));
}
__device__ __forceinline__ void mma_fp16(float* c, const uint32_t* a, uint32_t b0, uint32_t b1) {
    asm volatile(
        "mma.sync.aligned.m16n8k16.row.col.f32.f16.f16.f32 "
        "{%0,%1,%2,%3}, {%4,%5,%6,%7}, {%8,%9}, {%0,%1,%2,%3};"
        : "+f"(c[0]), "+f"(c[1]), "+f"(c[2]), "+f"(c[3])
        : "r"(a[0]), "r"(a[1]), "r"(a[2]), "r"(a[3]), "r"(b0), "r"(b1));
}
__device__ __forceinline__ void cpa16ca(uint32_t dst, const void* src) {
    asm volatile("cp.async.ca.shared.global [%0], [%1], 16;" :: "r"(dst), "l"(src));
}
__device__ __forceinline__ void cpa16cg(uint32_t dst, const void* src) {
    asm volatile("cp.async.cg.shared.global [%0], [%1], 16;" :: "r"(dst), "l"(src));
}
#define CP_COMMIT() asm volatile("cp.async.commit_group;")
#define CP_WAIT(n)  asm volatile("cp.async.wait_group %0;" :: "n"(n))

// ---------------------------------------------------------------------------
// Projection GEMM: plain fp16 1-pass Ah·Wh. occ 2.
// ---------------------------------------------------------------------------
#define KC 32
#define ROWP 40
#define BUF_E (128*ROWP)
#define OFF_AH 0
#define OFF_BH BUF_E
#define GEMM_SMEM_B (4*BUF_E*2 + 512)   // 41472 bytes

__device__ __forceinline__ void issue_op(uint32_t sdst, const __half* g,
                                         int tid, int k0) {
#pragma unroll
    for (int j = 0; j < 2; j++) {
        int u = tid + j * 256;
        int row = u >> 2, seg = u & 3;
        cpa16ca(sdst + (uint32_t)(row * ROWP + seg * 8) * 2,
                g + (size_t)row * DD + k0 + seg * 8);
    }
}

__global__ __launch_bounds__(256, 2) void gemm_kernel(const float* __restrict__ c_b,
                                                      const float* __restrict__ v_b) {
    extern __shared__ __half sm[];
    float* sBias = (float*)(sm + 4 * BUF_E);
    const uint32_t sbase = smem_u32(sm);

    const int tid  = threadIdx.x;
    const int lane = tid & 31;
    const int wid  = tid >> 5;
    const int wm   = wid >> 1;
    const int wn   = wid & 1;
    const int n0   = blockIdx.x * 128;
    const int m0   = blockIdx.y * 128;
    const int kind = n0 >> 10;

    const __half* Ah = g_Ah + (size_t)m0 * DD;
    const __half* Bh = g_Wh + (size_t)n0 * DD;

    const float* bp = (n0 < DD) ? (v_b + n0) : (c_b + (n0 - DD));
    if (tid < 128) sBias[tid] = bp[tid];

    float acc[2][8][4];
#pragma unroll
    for (int i = 0; i < 2; i++)
#pragma unroll
        for (int j = 0; j < 8; j++)
#pragma unroll
            for (int c = 0; c < 4; c++) acc[i][j][c] = 0.f;

    const int lrow_a = wm * 32 + (lane & 15);
    const int lrow_b0 = wn * 64 + (lane & 15);
    const int lk = ((lane >> 4) & 1) * 8;

    {
        issue_op(sbase + OFF_AH * 2, Ah, tid, 0);
        issue_op(sbase + OFF_BH * 2, Bh, tid, 0);
        CP_COMMIT();
    }

#pragma unroll 1
    for (int c = 0; c < DD / KC; c++) {
        const int cur = c & 1;
        if (c + 1 < DD / KC) {
            uint32_t bu = sbase + (uint32_t)((cur ^ 1) * 2 * BUF_E) * 2;
            int k0 = (c + 1) * KC;
            issue_op(bu + OFF_AH * 2, Ah, tid, k0);
            issue_op(bu + OFF_BH * 2, Bh, tid, k0);
            CP_COMMIT();
            CP_WAIT(1);
        } else {
            CP_WAIT(0);
        }
        __syncthreads();

        const __half* base = sm + cur * 2 * BUF_E;
#pragma unroll
        for (int kk = 0; kk < 2; kk++) {
            const int ke = kk * 16 + lk;
            uint32_t ah[2][4], bh[4][4];
#pragma unroll
            for (int mi = 0; mi < 2; mi++)
                ldsm_x4(ah[mi], smem_u32(base + OFF_AH + (lrow_a + mi * 16) * ROWP + ke));
#pragma unroll
            for (int nb = 0; nb < 4; nb++)
                ldsm_x4(bh[nb], smem_u32(base + OFF_BH + (lrow_b0 + nb * 16) * ROWP + ke));
#pragma unroll
            for (int mi = 0; mi < 2; mi++)
#pragma unroll
                for (int nb = 0; nb < 4; nb++) {
                    mma_fp16(acc[mi][nb*2+0], ah[mi], bh[nb][0], bh[nb][2]);
                    mma_fp16(acc[mi][nb*2+1], ah[mi], bh[nb][1], bh[nb][3]);
                }
        }
        __syncthreads();
    }

    const int h = (n0 >> 7) & 7;
    const int b_ = m0 >> 10;
    const int g = lane >> 2;
    const int tc = (lane & 3) * 2;
    const size_t bh_off = (size_t)(b_ * HH + h);

#pragma unroll
    for (int mi = 0; mi < 2; mi++) {
#pragma unroll
        for (int nj = 0; nj < 8; nj++) {
            const float* a4 = acc[mi][nj];
            int d = wn * 64 + nj * 8 + tc;
            float bx = sBias[d], by = sBias[d + 1];
            int s0 = (m0 + wm * 32 + mi * 16 + g) & 1023;
            float x0 = a4[0] + bx, x1 = a4[1] + by;
            float x2 = a4[2] + bx, x3 = a4[3] + by;
            if (kind == 2) {
                __half* dst = g_vth + bh_off * DH * SS;
                dst[(size_t)d * SS + s0]           = __float2half_rn(x0);
                dst[(size_t)(d + 1) * SS + s0]     = __float2half_rn(x1);
                dst[(size_t)d * SS + s0 + 8]       = __float2half_rn(x2);
                dst[(size_t)(d + 1) * SS + s0 + 8] = __float2half_rn(x3);
            } else {
                __half* dst = (kind == 0) ? g_kh : g_qh;
                size_t base_off = (bh_off * SS + s0) * DH + d;
                *(__half2*)(dst + base_off)          = __floats2half2_rn(x0, x1);
                *(__half2*)(dst + base_off + 8 * DH) = __floats2half2_rn(x2, x3);
            }
        }
    }
}

// ---------------------------------------------------------------------------
// Monolithic attention, TI=64, occ 2. fp16 1-pass scores (Kh·Qh).
// ---------------------------------------------------------------------------
#define KP 136
#define EPITCH 132                     // floats
#define VPITCH 136
#define PPITCH 136
#define SOFF_K    0                    // P1: Kh(17408) | P3: P(17408)
#define SOFF_U    17408                // P1: Qh(17408) | P3: E(33792)+V(34816)
#define SOFF_E    SOFF_U
#define SOFF_V    (SOFF_U + 33792)     // 51200
#define SOFF_MASK 86016
#define SOFF_SUM  90112                // 64 floats
#define SOFF_INV  90368                // 64 floats
#define ATTN_SMEM 90624

__global__ __launch_bounds__(256, 2) void attn_kernel(
    const float* __restrict__ m_feats,
    const int*   __restrict__ mask,
    float* __restrict__ out)
{
    extern __shared__ char smc[];
    int*   sMask = (int*)(smc + SOFF_MASK);
    float* sSum  = (float*)(smc + SOFF_SUM);
    float* sInv  = (float*)(smc + SOFF_INV);
    float*  sE  = (float*)(smc + SOFF_E);
    __half* sPh = (__half*)(smc + SOFF_K);
    const uint32_t uKh = smem_u32(smc) + SOFF_K;
    const uint32_t uQh = smem_u32(smc) + SOFF_U;
    const uint32_t uE  = smem_u32(smc) + SOFF_E;
    const uint32_t uV  = smem_u32(smc) + SOFF_V;
    const uint32_t uP  = smem_u32(smc) + SOFF_K;

    const int tid  = threadIdx.x;
    const int lane = tid & 31;
    const int wid  = tid >> 5;
    const int b  = blockIdx.z;
    const int h  = blockIdx.y;
    const int i0 = blockIdx.x * 64;
    const size_t bh = (size_t)(b * HH + h);
    const size_t wbase = (size_t)BB * SS * DD + (bh * SS + i0) * SS;

    const int wm = wid >> 2;        // 0..1
    const int wn = wid & 3;         // 0..3
    const int lr16 = lane & 15;
    const int lkb = (lane >> 4) * 8;
    const int grow = lane >> 2;
    const int gcol = (lane & 3) * 2;

    if (tid < 64) sSum[tid] = 0.f;
#pragma unroll
    for (int it = 0; it < 4; it++) {
        int p = tid + it * 256;
        int row = p >> 4, seg = p & 15;
        cpa16cg(uKh + (uint32_t)(row * KP + seg * 8) * 2,
                g_kh + (bh * SS + i0 + row) * DH + seg * 8);
    }
#pragma unroll
    for (int it = 0; it < 8; it++) {
        int p = tid + it * 256;
        int row = p >> 4, seg = p & 15;
        cpa16cg(uQh + (uint32_t)(row * KP + seg * 8) * 2,
                g_qh + (bh * SS + row) * DH + seg * 8);
    }
    CP_COMMIT();
    for (int j = tid; j < SS; j += 256) sMask[j] = mask[b * SS + j];

    // ================= Phase 1: e = exp(score) -> global; sums in regs ======
    float psum[2][2] = {{0.f, 0.f}, {0.f, 0.f}};
#pragma unroll 1
    for (int ct = 0; ct < 8; ct++) {
        CP_WAIT(0);
        __syncthreads();

        float acc[2][4][4];
#pragma unroll
        for (int i = 0; i < 2; i++)
#pragma unroll
            for (int j = 0; j < 4; j++)
#pragma unroll
                for (int cc = 0; cc < 4; cc++) acc[i][j][cc] = 0.f;

#pragma unroll
        for (int ks = 0; ks < 8; ks++) {
            const int ke = ks * 16 + lkb;
            uint32_t kh[2][4], qh[2][4];
#pragma unroll
            for (int mi = 0; mi < 2; mi++)
                ldsm_x4(kh[mi], uKh + (uint32_t)((wm * 32 + mi * 16 + lr16) * KP + ke) * 2);
#pragma unroll
            for (int nb = 0; nb < 2; nb++)
                ldsm_x4(qh[nb], uQh + (uint32_t)((wn * 32 + nb * 16 + lr16) * KP + ke) * 2);
#pragma unroll
            for (int mi = 0; mi < 2; mi++)
#pragma unroll
                for (int nb = 0; nb < 2; nb++) {
                    mma_fp16(acc[mi][nb*2+0], kh[mi], qh[nb][0], qh[nb][2]);
                    mma_fp16(acc[mi][nb*2+1], kh[mi], qh[nb][1], qh[nb][3]);
                }
        }

#pragma unroll
        for (int mi = 0; mi < 2; mi++)
#pragma unroll
            for (int nj = 0; nj < 4; nj++) {
                int jg = ct * 128 + wn * 32 + (nj >> 1) * 16 + (nj & 1) * 8 + gcol;
                bool m0 = sMask[jg] != 0, m1 = sMask[jg + 1] != 0;
                int ir = wm * 32 + mi * 16 + grow;
                const float* a4 = acc[mi][nj];
                float2 r0, r1;
                r0.x = m0 ? __expf(a4[0] * SCALE) : 1e-37f;
                r0.y = m1 ? __expf(a4[1] * SCALE) : 1e-37f;
                r1.x = m0 ? __expf(a4[2] * SCALE) : 1e-37f;
                r1.y = m1 ? __expf(a4[3] * SCALE) : 1e-37f;
                psum[mi][0] += r0.x + r0.y;
                psum[mi][1] += r1.x + r1.y;
                *(float2*)&out[wbase + (size_t)ir * SS + jg]       = r0;
                *(float2*)&out[wbase + (size_t)(ir + 8) * SS + jg] = r1;
            }
        __syncthreads();

        if (ct + 1 < 8) {
#pragma unroll
            for (int it = 0; it < 8; it++) {
                int p = tid + it * 256;
                int row = p >> 4, seg = p & 15;
                cpa16cg(uQh + (uint32_t)(row * KP + seg * 8) * 2,
                        g_qh + (bh * SS + (ct + 1) * 128 + row) * DH + seg * 8);
            }
            CP_COMMIT();
        }
    }

    // row-sum reduction -> sInv
#pragma unroll
    for (int mi = 0; mi < 2; mi++)
#pragma unroll
        for (int hf = 0; hf < 2; hf++) {
            psum[mi][hf] += __shfl_xor_sync(~0u, psum[mi][hf], 1);
            psum[mi][hf] += __shfl_xor_sync(~0u, psum[mi][hf], 2);
        }
    if ((lane & 3) == 0) {
#pragma unroll
        for (int mi = 0; mi < 2; mi++) {
            atomicAdd(&sSum[wm * 32 + mi * 16 + grow],     psum[mi][0]);
            atomicAdd(&sSum[wm * 32 + mi * 16 + grow + 8], psum[mi][1]);
        }
    }
    __syncthreads();
    if (tid < 64) sInv[tid] = 1.0f / sSum[tid];
    __threadfence_block();
    __syncthreads();

    // ================= Phase 3: pipelined normalize + PV (fp16) =============
    float racc[2][4][4];
#pragma unroll
    for (int i = 0; i < 2; i++)
#pragma unroll
        for (int j = 0; j < 4; j++)
#pragma unroll
            for (int cc = 0; cc < 4; cc++) racc[i][j][cc] = 0.f;

    const int crow = tid >> 2;          // 0..63
    const int cq   = tid & 3;

#pragma unroll
    for (int it = 0; it < 8; it++) {
        int p = tid + it * 256;
        int row = p >> 5, seg = p & 31;
        cpa16cg(uE + (uint32_t)(row * EPITCH + seg * 4) * 4,
                out + wbase + (size_t)row * SS + seg * 4);
    }
    CP_COMMIT();
#pragma unroll
    for (int it = 0; it < 8; it++) {
        int p = tid + it * 256;
        int row = p >> 4, seg = p & 15;
        cpa16cg(uV + (uint32_t)(row * VPITCH + seg * 8) * 2,
                g_vth + (bh * DH + row) * SS + seg * 8);
    }
    CP_COMMIT();

#pragma unroll 1
    for (int jc = 0; jc < 8; jc++) {
        CP_WAIT(1);                 // E_jc ready
        __syncthreads();

        {
            float inv = sInv[crow];
            const float* erow = sE + crow * EPITCH;
            float* wrow = out + wbase + (size_t)crow * SS + jc * 128;
#pragma unroll
            for (int k = 0; k < 8; k++) {
                int col = cq * 4 + k * 16;
                float4 e4 = *(const float4*)&erow[col];
                float4 w4;
                w4.x = e4.x * inv; w4.y = e4.y * inv;
                w4.z = e4.z * inv; w4.w = e4.w * inv;
                *(float4*)&wrow[col] = w4;
                union { uint2 u; __half2 h2[2]; } pk;
                pk.h2[0] = __floats2half2_rn(w4.x, w4.y);
                pk.h2[1] = __floats2half2_rn(w4.z, w4.w);
                *(uint2*)&sPh[crow * PPITCH + col] = pk.u;
            }
        }
        __syncthreads();

        if (jc + 1 < 8) {
#pragma unroll
            for (int it = 0; it < 8; it++) {
                int p = tid + it * 256;
                int row = p >> 5, seg = p & 31;
                cpa16cg(uE + (uint32_t)(row * EPITCH + seg * 4) * 4,
                        out + wbase + (size_t)row * SS + (jc + 1) * 128 + seg * 4);
            }
            CP_COMMIT();
        }

        CP_WAIT(1);                 // V_jc ready
        __syncthreads();

#pragma unroll
        for (int ks = 0; ks < 8; ks++) {
            const int ke = ks * 16 + lkb;
            uint32_t pa[2][4], vh[2][4];
#pragma unroll
            for (int mi = 0; mi < 2; mi++)
                ldsm_x4(pa[mi], uP + (uint32_t)((wm * 32 + mi * 16 + lr16) * PPITCH + ke) * 2);
#pragma unroll
            for (int nb = 0; nb < 2; nb++)
                ldsm_x4(vh[nb], uV + (uint32_t)((wn * 32 + nb * 16 + lr16) * VPITCH + ke) * 2);
#pragma unroll
            for (int mi = 0; mi < 2; mi++)
#pragma unroll
                for (int nb = 0; nb < 2; nb++) {
                    mma_fp16(racc[mi][nb*2+0], pa[mi], vh[nb][0], vh[nb][2]);
                    mma_fp16(racc[mi][nb*2+1], pa[mi], vh[nb][1], vh[nb][3]);
                }
        }
        __syncthreads();

        if (jc + 1 < 8) {
#pragma unroll
            for (int it = 0; it < 8; it++) {
                int p = tid + it * 256;
                int row = p >> 4, seg = p & 15;
                cpa16cg(uV + (uint32_t)(row * VPITCH + seg * 8) * 2,
                        g_vth + (bh * DH + row) * SS + (jc + 1) * 128 + seg * 8);
            }
            CP_COMMIT();
        }
    }

    // epilogue: out = m_feats + R
#pragma unroll
    for (int mi = 0; mi < 2; mi++)
#pragma unroll
        for (int nj = 0; nj < 4; nj++) {
            int d = wn * 32 + (nj >> 1) * 16 + (nj & 1) * 8 + gcol;
            int ir = wm * 32 + mi * 16 + grow;
            const float* a4 = racc[mi][nj];
            size_t o0 = ((size_t)b * SS + i0 + ir) * DD + h * DH + d;
            float2 mf0 = *(const float2*)&m_feats[o0];
            *(float2*)&out[o0] = make_float2(mf0.x + a4[0], mf0.y + a4[1]);
            size_t o1 = o0 + (size_t)8 * DD;
            float2 mf1 = *(const float2*)&m_feats[o1];
            *(float2*)&out[o1] = make_float2(mf1.x + a4[2], mf1.y + a4[3]);
        }
}

// ---------------------------------------------------------------------------
extern "C" void kernel_launch(void* const* d_in, const int* in_sizes, int n_in,
                              void* d_out, int out_size)
{
    const float* m_feats = (const float*)d_in[0];
    const int*   mask    = (const int*)d_in[1];
    const float* c_w     = (const float*)d_in[2];
    const float* c_b     = (const float*)d_in[3];
    const float* v_w     = (const float*)d_in[4];
    const float* v_b     = (const float*)d_in[5];
    float* out = (float*)d_out;

    conv_kernel<<<(A_I4 + W_I4 + 255) / 256, 256>>>(m_feats, c_w, v_w);

    cudaFuncSetAttribute(gemm_kernel,
                         cudaFuncAttributeMaxDynamicSharedMemorySize, GEMM_SMEM_B);
    dim3 gG(NN / 128, BB * SS / 128);
    gemm_kernel<<<gG, 256, GEMM_SMEM_B>>>(c_b, v_b);

    cudaFuncSetAttribute(attn_kernel,
                         cudaFuncAttributeMaxDynamicSharedMemorySize, ATTN_SMEM);
    dim3 gB(SS / 64, HH, BB);
    attn_kernel<<<gB, 256, ATTN_SMEM>>>(m_feats, mask, out);
}